// round 13
// baseline (speedup 1.0000x reference)
#include <cuda_runtime.h>
#include <cuda_fp16.h>
#include <math.h>
#include <stdint.h>

// ---------------------------------------------------------------------------
// CortexBlock on GB300 (compute_103 pipeline => mma.sync HMMA path)
// B=4, T=2048, D=1024, H=16, Dh=64, R=16
// R11 GEMMs + staged scan re-partitioned: warp g owns ALL 64 d for
// r in [8g, 8g+8)  =>  ku reduction is intra-warp (shuffles only); the
// cross-warp kf/score exchange is deferred one step (off the state chain).
// ---------------------------------------------------------------------------

#define D_MODEL 1024
#define N_HEADS 16
#define D_HEAD  64
#define RANK    16
#define RHALF   8
#define DECAY   0.95f
#define ALPHA_MAX 0.05f
#define BETA    0.01f

#define BB 4
#define TT 2048
#define BT (BB*TT)   // 8192

// ---------------- scratch (static device globals; no allocs allowed) -------
__device__ __align__(256) __half g_xh[BT * D_MODEL];
__device__ __align__(256) __half g_w[4 * D_MODEL * D_MODEL];   // Wq,Wk,Wv,Wo fp16
__device__ __align__(256) __half g_yh[BT * D_MODEL];
__device__ __align__(256) float g_q[BT * D_MODEL];
__device__ __align__(256) float g_k[BT * D_MODEL];
__device__ __align__(256) float g_v[BT * D_MODEL];
__device__ __align__(256) float g_alpha[BT * N_HEADS];

// ---------------- small asm helpers ----------------------------------------
__device__ __forceinline__ uint32_t smem_u32(const void* p) {
    uint32_t a;
    asm("{ .reg .u64 t; cvta.to.shared.u64 t, %1; cvt.u32.u64 %0, t; }"
        : "=r"(a) : "l"(p));
    return a;
}
__device__ __forceinline__ void cp_async16(uint32_t daddr, const void* gaddr) {
    asm volatile("cp.async.cg.shared.global [%0], [%1], 16;"
                 :: "r"(daddr), "l"(gaddr) : "memory");
}
__device__ __forceinline__ void cp_async4(uint32_t daddr, const void* gaddr) {
    asm volatile("cp.async.ca.shared.global [%0], [%1], 4;"
                 :: "r"(daddr), "l"(gaddr) : "memory");
}
#define CP_COMMIT()  asm volatile("cp.async.commit_group;" ::: "memory")
#define CP_WAIT(n)   asm volatile("cp.async.wait_group %0;" :: "n"(n) : "memory")

__device__ __forceinline__ void ldsm_x4(uint32_t (&r)[4], uint32_t addr) {
    asm volatile("ldmatrix.sync.aligned.m8n8.x4.shared.b16 {%0,%1,%2,%3}, [%4];"
                 : "=r"(r[0]), "=r"(r[1]), "=r"(r[2]), "=r"(r[3]) : "r"(addr));
}
__device__ __forceinline__ void mma_16816_f16(float (&d)[4], const uint32_t (&a)[4],
                                              uint32_t b0, uint32_t b1) {
    asm volatile(
        "mma.sync.aligned.m16n8k16.row.col.f32.f16.f16.f32 "
        "{%0,%1,%2,%3}, {%4,%5,%6,%7}, {%8,%9}, {%0,%1,%2,%3};"
        : "+f"(d[0]), "+f"(d[1]), "+f"(d[2]), "+f"(d[3])
        : "r"(a[0]), "r"(a[1]), "r"(a[2]), "r"(a[3]), "r"(b0), "r"(b1));
}

// ---------------------------------------------------------------------------
// fp16 single-pass GEMM (R8 config): C[M,N](fp32) = A[M,K] * W[N,K]^T
// CTA tile 128x128, K-chunk 64, 4-stage cp.async, 1 barrier/chunk.
// ---------------------------------------------------------------------------
#define GM 128
#define GN 128
#define GKC 64
#define AST 72
#define TILE_HALVES (GM * AST)            // 9216 halves = 18432 B
#define TILE_BYTES  (TILE_HALVES * 2)
#define STAGE_BYTES (2 * TILE_BYTES)      // 36864
#define NSTAGE 4
#define GEMM_SMEM_BYTES (NSTAGE * STAGE_BYTES)   // 147456

__global__ __launch_bounds__(256, 1) void gemm_f16(
    const __half* __restrict__ A, const __half* __restrict__ Wbase,
    float* __restrict__ C0, float* __restrict__ C1, float* __restrict__ C2,
    int M, int N, int K)
{
    extern __shared__ __half smem[];

    const int tid  = threadIdx.x;
    const int wid  = tid >> 5;
    const int lane = tid & 31;
    const int rowBase = blockIdx.y * GM;
    const int colBase = blockIdx.x * GN;
    const int z = blockIdx.z;

    const __half* Bw = Wbase + (size_t)z * D_MODEL * D_MODEL;
    float* C = (z == 0) ? C0 : (z == 1) ? C1 : C2;

    const int wm = (wid >> 2) * 64;
    const int wn = (wid & 3) * 32;

    const uint32_t smBase = smem_u32(smem);

    float acc[4][4][4];
#pragma unroll
    for (int i = 0; i < 4; i++)
#pragma unroll
        for (int j = 0; j < 4; j++)
#pragma unroll
            for (int c = 0; c < 4; c++) acc[i][j][c] = 0.0f;

    const int aRow = lane & 15;
    const int aKo  = (lane >> 4) * 8;
    const int bNo  = ((lane >> 4) << 3) + (lane & 7);
    const int bKo  = ((lane >> 3) & 1) * 8;

    const int NCH = K / GKC;              // 16

    auto issue = [&](int ci) {
        const int k0 = ci * GKC;
        const uint32_t stage = smBase + (uint32_t)(ci % NSTAGE) * STAGE_BYTES;
#pragma unroll
        for (int i = 0; i < 4; i++) {
            int L = tid + (i << 8);
            int row = L >> 3;
            int seg = L & 7;
            uint32_t off = (uint32_t)row * (AST * 2) + seg * 16;
            cp_async16(stage + off,
                       A + (size_t)(rowBase + row) * K + k0 + seg * 8);
            cp_async16(stage + TILE_BYTES + off,
                       Bw + (size_t)(colBase + row) * K + k0 + seg * 8);
        }
        CP_COMMIT();
    };

    issue(0);
    issue(1);
    issue(2);

    for (int ci = 0; ci < NCH; ci++) {
        CP_WAIT(2);
        __syncthreads();
        if (ci + 3 < NCH) issue(ci + 3);
        else CP_COMMIT();

        const uint32_t stage  = smBase + (uint32_t)(ci % NSTAGE) * STAGE_BYTES;
        const uint32_t bBase0 = stage + TILE_BYTES;

#pragma unroll
        for (int ks = 0; ks < 4; ks++) {
            uint32_t Ar[4][4];
#pragma unroll
            for (int mi = 0; mi < 4; mi++) {
                uint32_t addr = stage + (uint32_t)(wm + mi * 16 + aRow) * (AST * 2)
                              + (uint32_t)(ks * 16 + aKo) * 2;
                ldsm_x4(Ar[mi], addr);
            }
            uint32_t Br[2][4];
#pragma unroll
            for (int ni = 0; ni < 2; ni++) {
                uint32_t addr = bBase0 + (uint32_t)(wn + ni * 16 + bNo) * (AST * 2)
                              + (uint32_t)(ks * 16 + bKo) * 2;
                ldsm_x4(Br[ni], addr);
            }
#pragma unroll
            for (int mi = 0; mi < 4; mi++)
#pragma unroll
                for (int j = 0; j < 4; j++)
                    mma_16816_f16(acc[mi][j], Ar[mi],
                                  Br[j >> 1][(j & 1) * 2], Br[j >> 1][(j & 1) * 2 + 1]);
        }
    }

#pragma unroll
    for (int mi = 0; mi < 4; mi++) {
        const int row0 = rowBase + wm + mi * 16 + (lane >> 2);
#pragma unroll
        for (int j = 0; j < 4; j++) {
            const int col = colBase + wn + j * 8 + (lane & 3) * 2;
            *reinterpret_cast<float2*>(C + (size_t)row0 * N + col) =
                make_float2(acc[mi][j][0], acc[mi][j][1]);
            *reinterpret_cast<float2*>(C + (size_t)(row0 + 8) * N + col) =
                make_float2(acc[mi][j][2], acc[mi][j][3]);
        }
    }
}

// ---------------------------------------------------------------------------
// Fused x->fp16 convert + alpha (R8). Block = 16 rows, 512 threads.
// ---------------------------------------------------------------------------
__global__ __launch_bounds__(512) void cvtx_alpha_kernel(
    const float* __restrict__ x, const float* __restrict__ Wa,
    const float* __restrict__ ba, const float* __restrict__ m_gate,
    const float* __restrict__ ascale,
    __half* __restrict__ xh, float* __restrict__ alpha)
{
    extern __shared__ float xs[];        // [16][1024]
    const int tid  = threadIdx.x;
    const int warp = tid >> 5;
    const int lane = tid & 31;
    const int rowBase = blockIdx.x * 16;

    const float4* xg = reinterpret_cast<const float4*>(x + (size_t)rowBase * D_MODEL);
#pragma unroll
    for (int it = 0; it < 8; it++) {
        int i = tid + it * 512;
        float4 v = xg[i];
        reinterpret_cast<float4*>(xs)[i] = v;
        __half2* ph = reinterpret_cast<__half2*>(xh + (size_t)rowBase * D_MODEL + i * 4);
        ph[0] = __half2(__float2half_rn(v.x), __float2half_rn(v.y));
        ph[1] = __half2(__float2half_rn(v.z), __float2half_rn(v.w));
    }
    __syncthreads();

    float wa[32];
#pragma unroll
    for (int i = 0; i < 32; i++)
        wa[i] = Wa[(size_t)warp * D_MODEL + i * 32 + lane];
    const float bw = ba[warp];

#pragma unroll 4
    for (int row = 0; row < 16; row++) {
        const float* xr = xs + row * D_MODEL;
        float s = 0.0f;
#pragma unroll
        for (int i = 0; i < 32; i++)
            s = fmaf(wa[i], xr[i * 32 + lane], s);
#pragma unroll
        for (int off = 16; off; off >>= 1)
            s += __shfl_xor_sync(0xFFFFFFFFu, s, off);
        if (lane == 0) {
            const int r = rowBase + row;
            float sg = __fdividef(1.0f, 1.0f + __expf(-(s + bw)));
            float a = sg * m_gate[r] * ascale[(size_t)r * N_HEADS + warp];
            alpha[(size_t)r * N_HEADS + warp] = fminf(a, ALPHA_MAX);
        }
    }
}

// ---------------------------------------------------------------------------
// Round all 4 weight matrices to fp16 in one launch.
// ---------------------------------------------------------------------------
__global__ __launch_bounds__(256) void cvt4_kernel(
    const float* __restrict__ W0, const float* __restrict__ W1,
    const float* __restrict__ W2, const float* __restrict__ W3,
    __half* __restrict__ out)
{
    const int i = blockIdx.x * 256 + threadIdx.x;
    const int sel = i >> 20;
    const int off = i & ((1 << 20) - 1);
    const float* src = (sel == 0) ? W0 : (sel == 1) ? W1 : (sel == 2) ? W2 : W3;
    out[i] = __float2half_rn(src[off]);
}

// ---------------------------------------------------------------------------
// Sequential fast-weight scan, 64 threads = 2 warps.
// Warp g owns r in [8g, 8g+8) for ALL 64 d; lane owns d0=lane, d1=lane+32.
// ku is intra-warp (3-level compaction + xor8/xor16 + 8 idx-broadcasts).
// kf halves + s1 partial exchanged via smem ONE STEP LATE (off the chain);
// warp0 finalizes y(t-1). cp.async staging identical to R11.
// ---------------------------------------------------------------------------
#define SCH 16   // timesteps per staging chunk

__global__ __launch_bounds__(64) void scan_kernel(
    const float* __restrict__ q, const float* __restrict__ k,
    const float* __restrict__ v, const float* __restrict__ alpha,
    __half* __restrict__ yh, int T)
{
    const int bh = blockIdx.x;
    const int b = bh / N_HEADS;
    const int h = bh % N_HEADS;
    const int tid = threadIdx.x;          // 0..63
    const int warp = tid >> 5;            // r-group
    const int lane = tid & 31;
    const int d0 = lane;
    const int d1 = lane + 32;

    __shared__ float sq[2][SCH][D_HEAD];
    __shared__ float sk[2][SCH][D_HEAD];
    __shared__ float sv[2][SCH][D_HEAD];
    __shared__ float sa[2][SCH];
    __shared__ float sm_kf[2][D_HEAD];    // warp1's kf partial per d
    __shared__ float sm_s1[2];            // warp1's s1 partial

    const uint32_t sq_a = smem_u32(sq);
    const uint32_t sk_a = smem_u32(sk);
    const uint32_t sv_a = smem_u32(sv);
    const uint32_t sa_a = smem_u32(sa);

    // state: U[d][r], V[r][d] for d in {d0,d1}, r in [8*warp, 8*warp+8)
    float U0[RHALF], U1[RHALF], V0[RHALF], V1[RHALF];
#pragma unroll
    for (int r = 0; r < RHALF; r++) { U0[r] = U1[r] = V0[r] = V1[r] = 0.0f; }

    // after 3-level compaction, lane L holds r_local = bitrev3(L & 7);
    // broadcast source lane for r is BREV3[r] (involution).
    static const int BREV3[RHALF] = {0, 4, 2, 6, 1, 5, 3, 7};

    const size_t strideT = (size_t)N_HEADS * D_HEAD;   // 1024
    const size_t qbase = (size_t)b * T * strideT + (size_t)h * D_HEAD;
    const size_t abase = (size_t)b * T * N_HEADS + h;

    // chunk loader (64 threads): 256 x 16B per array, 4 per thread
    auto issue = [&](int c) {
        const int t0 = c * SCH;
        const uint32_t bufB = (uint32_t)(c & 1) * (SCH * D_HEAD * 4);
#pragma unroll
        for (int i = 0; i < 4; i++) {
            int L = tid + (i << 6);          // 0..255
            int s = L >> 4;
            int seg = L & 15;
            const size_t g = qbase + (size_t)(t0 + s) * strideT + seg * 4;
            const uint32_t so = bufB + (uint32_t)s * (D_HEAD * 4) + seg * 16;
            cp_async16(sq_a + so, q + g);
            cp_async16(sk_a + so, k + g);
            cp_async16(sv_a + so, v + g);
        }
        if (tid < SCH)
            cp_async4(sa_a + (uint32_t)(c & 1) * (SCH * 4) + tid * 4,
                      alpha + abase + (size_t)(t0 + tid) * N_HEADS);
        CP_COMMIT();
    };

    issue(0);
    issue(1);

    // deferred (step t-1) values
    float sp0 = 0.f, sp1 = 0.f;           // own-warp scores of step t-1
    float v0p = 0.f, v1p = 0.f, kf0p = 0.f, kf1p = 0.f;
    size_t yidxprev = 0;
    const int NCHK = T / SCH;              // 128

    for (int c = 0; c < NCHK; c++) {
        CP_WAIT(1);
        __syncthreads();
        const int buf = c & 1;
        const int t0 = c * SCH;

        float qt0 = sq[buf][0][d0], qt1 = sq[buf][0][d1];
        float kt0 = sk[buf][0][d0], kt1 = sk[buf][0][d1];
        float vt0 = sv[buf][0][d0], vt1 = sv[buf][0][d1];
        float a   = sa[buf][0];

#pragma unroll 4
        for (int s = 0; s < SCH; s++) {
            const int t = t0 + s;

            // prefetch next step (off-chain LDS)
            float nq0 = 0.f, nq1 = 0.f, nk0 = 0.f, nk1 = 0.f;
            float nv0 = 0.f, nv1 = 0.f, na = 0.f;
            if (s + 1 < SCH) {
                nq0 = sq[buf][s + 1][d0]; nq1 = sq[buf][s + 1][d1];
                nk0 = sk[buf][s + 1][d0]; nk1 = sk[buf][s + 1][d1];
                nv0 = sv[buf][s + 1][d0]; nv1 = sv[buf][s + 1][d1];
                na  = sa[buf][s + 1];
            }

            // p partials (decay folded): p[r] = sum over this lane's 2 d
            const float ktd0 = kt0 * DECAY;
            const float ktd1 = kt1 * DECAY;
            float p[RHALF];
#pragma unroll
            for (int r = 0; r < RHALF; r++)
                p[r] = fmaf(ktd1, U1[r], ktd0 * U0[r]);

            // intra-warp: 3-level compaction over 8 + xor8 + xor16
#pragma unroll
            for (int st = 1, cnt = 4; st <= 4; st <<= 1, cnt >>= 1) {
                const bool hi = (lane & st) != 0;
#pragma unroll
                for (int i = 0; i < cnt; i++) {
                    float lo_v = p[i], hi_v = p[i + cnt];
                    float send = hi ? lo_v : hi_v;
                    float recv = __shfl_xor_sync(0xFFFFFFFFu, send, st);
                    p[i] = (hi ? hi_v : lo_v) + recv;
                }
            }
            float vr = p[0];
            vr += __shfl_xor_sync(0xFFFFFFFFu, vr, 8);
            vr += __shfl_xor_sync(0xFFFFFFFFu, vr, 16);

            // decay overlaps the tree
#pragma unroll
            for (int r = 0; r < RHALF; r++) {
                U0[r] *= DECAY; U1[r] *= DECAY;
                V0[r] *= DECAY; V1[r] *= DECAY;
            }

            // broadcast ku (8 independent shfls; no barrier, no smem)
            float ku[RHALF];
#pragma unroll
            for (int r = 0; r < RHALF; r++)
                ku[r] = __shfl_sync(0xFFFFFFFFu, vr, BREV3[r]);

            const float ak0 = a * kt0, ak1 = a * kt1;
            const float av0 = a * vt0, av1 = a * vt1;
            float kf0a = 0.f, kf0b = 0.f, kf1a = 0.f, kf1b = 0.f;
#pragma unroll
            for (int r = 0; r < RHALF; r++) {
                float u0 = fmaf(ak0, ku[r], U0[r]);
                float u1 = fmaf(ak1, ku[r], U1[r]);
                float w0 = fmaf(av0, ku[r], V0[r]);
                float w1 = fmaf(av1, ku[r], V1[r]);
                u0 -= BETA * fminf(fmaxf(u0, -1.0f), 1.0f);
                u1 -= BETA * fminf(fmaxf(u1, -1.0f), 1.0f);
                w0 -= BETA * fminf(fmaxf(w0, -1.0f), 1.0f);
                w1 -= BETA * fminf(fmaxf(w1, -1.0f), 1.0f);
                U0[r] = u0; U1[r] = u1; V0[r] = w0; V1[r] = w1;
                if (r & 1) { kf0b = fmaf(u0, w0, kf0b); kf1b = fmaf(u1, w1, kf1b); }
                else       { kf0a = fmaf(u0, w0, kf0a); kf1a = fmaf(u1, w1, kf1a); }
            }
            const float kf0 = kf0a + kf0b;   // this warp's r-half, d0
            const float kf1 = kf1a + kf1b;   // this warp's r-half, d1

            // scores: s0 full (both warps have all d), s1 own-half partial
            const float qn0 = qt0 * 0.125f;
            const float qn1 = qt1 * 0.125f;
            float s0 = fmaf(qn1, kt1, qn0 * kt0);
            float s1 = fmaf(qn1, kf1, qn0 * kf0);
#pragma unroll
            for (int off = 16; off; off >>= 1) {
                s0 += __shfl_xor_sync(0xFFFFFFFFu, s0, off);
                s1 += __shfl_xor_sync(0xFFFFFFFFu, s1, off);
            }

            __syncthreads();   // orders prev-step writes; off the state chain
            if (warp == 1) {
                sm_kf[t & 1][d0] = kf0;
                sm_kf[t & 1][d1] = kf1;
                if (lane == 0) sm_s1[t & 1] = s1;
            } else if (t > 0) {
                // finalize y(t-1): warp1's step-(t-1) data in slot (t-1)&1
                const float S1 = sp1 + sm_s1[(t - 1) & 1];
                const float m1 = __fdividef(1.0f, 1.0f + __expf(sp0 - S1));
                const float m0 = 1.0f - m1;
                const float kfF0 = kf0p + sm_kf[(t - 1) & 1][d0];
                const float kfF1 = kf1p + sm_kf[(t - 1) & 1][d1];
                yh[yidxprev]      = __float2half_rn(m0 * v0p + m1 * kfF0);
                yh[yidxprev + 32] = __float2half_rn(m0 * v1p + m1 * kfF1);
            }

            sp0 = s0; sp1 = s1;
            v0p = vt0; v1p = vt1; kf0p = kf0; kf1p = kf1;
            yidxprev = qbase + (size_t)t * strideT + d0;

            qt0 = nq0; qt1 = nq1; kt0 = nk0; kt1 = nk1;
            vt0 = nv0; vt1 = nv1; a = na;
        }

        __syncthreads();                   // staging buffer reuse safety
        if (c + 2 < NCHK) issue(c + 2);
        else CP_COMMIT();
    }

    // tail: finalize y(T-1); warp1's last write already ordered by the
    // trailing chunk barrier above.
    if (warp == 0) {
        const float S1 = sp1 + sm_s1[(T - 1) & 1];
        const float m1 = __fdividef(1.0f, 1.0f + __expf(sp0 - S1));
        const float m0 = 1.0f - m1;
        const float kfF0 = kf0p + sm_kf[(T - 1) & 1][d0];
        const float kfF1 = kf1p + sm_kf[(T - 1) & 1][d1];
        yh[yidxprev]      = __float2half_rn(m0 * v0p + m1 * kfF0);
        yh[yidxprev + 32] = __float2half_rn(m0 * v1p + m1 * kfF1);
    }
}

// ---------------------------------------------------------------------------
// Launch (single stream, R11 sequence)
// ---------------------------------------------------------------------------
extern "C" void kernel_launch(void* const* d_in, const int* in_sizes, int n_in,
                              void* d_out, int out_size)
{
    const float* x      = (const float*)d_in[0];
    const float* m_gate = (const float*)d_in[1];
    const float* ascale = (const float*)d_in[2];
    const float* Wq     = (const float*)d_in[3];
    const float* Wk     = (const float*)d_in[4];
    const float* Wv     = (const float*)d_in[5];
    const float* Wo     = (const float*)d_in[6];
    const float* Wa     = (const float*)d_in[7];
    const float* ba     = (const float*)d_in[8];
    // d_in[9] = mix_logit: cancels in the 2-way softmax; unused.
    float* out = (float*)d_out;

    const int M = in_sizes[1] > 0 ? in_sizes[1] : BT;  // B*T
    const int T = M / BB;

    __half *xh, *wf, *yh;
    float *dq, *dk, *dv, *da;
    cudaGetSymbolAddress((void**)&xh, g_xh);
    cudaGetSymbolAddress((void**)&wf, g_w);
    cudaGetSymbolAddress((void**)&yh, g_yh);
    cudaGetSymbolAddress((void**)&dq, g_q);
    cudaGetSymbolAddress((void**)&dk, g_k);
    cudaGetSymbolAddress((void**)&dv, g_v);
    cudaGetSymbolAddress((void**)&da, g_alpha);

    const int DW = D_MODEL * D_MODEL;

    static bool attr_set = false;
    if (!attr_set) {
        cudaFuncSetAttribute(gemm_f16,
                             cudaFuncAttributeMaxDynamicSharedMemorySize, GEMM_SMEM_BYTES);
        cudaFuncSetAttribute(cvtx_alpha_kernel,
                             cudaFuncAttributeMaxDynamicSharedMemorySize, 16 * D_MODEL * 4);
        attr_set = true;
    }

    cvtx_alpha_kernel<<<M / 16, 512, 16 * D_MODEL * 4>>>(
        x, Wa, ba, m_gate, ascale, xh, da);

    cvt4_kernel<<<(4 * DW) / 256, 256>>>(Wq, Wk, Wv, Wo, wf);

    dim3 gqkv(D_MODEL / GN, M / GM, 3);
    gemm_f16<<<gqkv, 256, GEMM_SMEM_BYTES>>>(xh, wf, dq, dk, dv, M, D_MODEL, D_MODEL);

    scan_kernel<<<BB * N_HEADS, 64>>>(dq, dk, dv, da, yh, T);

    dim3 go(D_MODEL / GN, M / GM, 1);
    gemm_f16<<<go, 256, GEMM_SMEM_BYTES>>>(yh, wf + (size_t)3 * DW,
                                           out, out, out, M, D_MODEL, D_MODEL);
}

// round 14
// speedup vs baseline: 1.2707x; 1.2707x over previous
#include <cuda_runtime.h>
#include <cuda_fp16.h>
#include <math.h>
#include <stdint.h>

// ---------------------------------------------------------------------------
// CortexBlock on GB300 (compute_103 pipeline => mma.sync HMMA path)
// B=4, T=2048, D=1024, H=16, Dh=64, R=16
// R11 GEMMs + R11 staged scan with packed f32x2 arithmetic (fma-pipe ops
// nearly halved; clip stays scalar FMNMX on the alu pipe).
// ---------------------------------------------------------------------------

#define D_MODEL 1024
#define N_HEADS 16
#define D_HEAD  64
#define RANK    16
#define DECAY   0.95f
#define ALPHA_MAX 0.05f
#define BETA    0.01f

#define BB 4
#define TT 2048
#define BT (BB*TT)   // 8192

// ---------------- scratch (static device globals; no allocs allowed) -------
__device__ __align__(256) __half g_xh[BT * D_MODEL];
__device__ __align__(256) __half g_w[4 * D_MODEL * D_MODEL];   // Wq,Wk,Wv,Wo fp16
__device__ __align__(256) __half g_yh[BT * D_MODEL];
__device__ __align__(256) float g_q[BT * D_MODEL];
__device__ __align__(256) float g_k[BT * D_MODEL];
__device__ __align__(256) float g_v[BT * D_MODEL];
__device__ __align__(256) float g_alpha[BT * N_HEADS];

// ---------------- small asm helpers ----------------------------------------
typedef unsigned long long u64t;
__device__ __forceinline__ u64t pack2(float lo, float hi) {
    u64t r; asm("mov.b64 %0, {%1, %2};" : "=l"(r) : "f"(lo), "f"(hi)); return r;
}
__device__ __forceinline__ void unpack2(u64t p, float& lo, float& hi) {
    asm("mov.b64 {%0, %1}, %2;" : "=f"(lo), "=f"(hi) : "l"(p));
}
__device__ __forceinline__ u64t fma2(u64t a, u64t b, u64t c) {
    u64t d; asm("fma.rn.f32x2 %0, %1, %2, %3;" : "=l"(d) : "l"(a), "l"(b), "l"(c)); return d;
}
__device__ __forceinline__ u64t mul2(u64t a, u64t b) {
    u64t d; asm("mul.rn.f32x2 %0, %1, %2;" : "=l"(d) : "l"(a), "l"(b)); return d;
}
__device__ __forceinline__ u64t add2(u64t a, u64t b) {
    u64t d; asm("add.rn.f32x2 %0, %1, %2;" : "=l"(d) : "l"(a), "l"(b)); return d;
}

__device__ __forceinline__ uint32_t smem_u32(const void* p) {
    uint32_t a;
    asm("{ .reg .u64 t; cvta.to.shared.u64 t, %1; cvt.u32.u64 %0, t; }"
        : "=r"(a) : "l"(p));
    return a;
}
__device__ __forceinline__ void cp_async16(uint32_t daddr, const void* gaddr) {
    asm volatile("cp.async.cg.shared.global [%0], [%1], 16;"
                 :: "r"(daddr), "l"(gaddr) : "memory");
}
__device__ __forceinline__ void cp_async4(uint32_t daddr, const void* gaddr) {
    asm volatile("cp.async.ca.shared.global [%0], [%1], 4;"
                 :: "r"(daddr), "l"(gaddr) : "memory");
}
#define CP_COMMIT()  asm volatile("cp.async.commit_group;" ::: "memory")
#define CP_WAIT(n)   asm volatile("cp.async.wait_group %0;" :: "n"(n) : "memory")

__device__ __forceinline__ void ldsm_x4(uint32_t (&r)[4], uint32_t addr) {
    asm volatile("ldmatrix.sync.aligned.m8n8.x4.shared.b16 {%0,%1,%2,%3}, [%4];"
                 : "=r"(r[0]), "=r"(r[1]), "=r"(r[2]), "=r"(r[3]) : "r"(addr));
}
__device__ __forceinline__ void mma_16816_f16(float (&d)[4], const uint32_t (&a)[4],
                                              uint32_t b0, uint32_t b1) {
    asm volatile(
        "mma.sync.aligned.m16n8k16.row.col.f32.f16.f16.f32 "
        "{%0,%1,%2,%3}, {%4,%5,%6,%7}, {%8,%9}, {%0,%1,%2,%3};"
        : "+f"(d[0]), "+f"(d[1]), "+f"(d[2]), "+f"(d[3])
        : "r"(a[0]), "r"(a[1]), "r"(a[2]), "r"(a[3]), "r"(b0), "r"(b1));
}

// ---------------------------------------------------------------------------
// fp16 single-pass GEMM (R8 config): C[M,N](fp32) = A[M,K] * W[N,K]^T
// CTA tile 128x128, K-chunk 64, 4-stage cp.async, 1 barrier/chunk.
// ---------------------------------------------------------------------------
#define GM 128
#define GN 128
#define GKC 64
#define AST 72
#define TILE_HALVES (GM * AST)            // 9216 halves = 18432 B
#define TILE_BYTES  (TILE_HALVES * 2)
#define STAGE_BYTES (2 * TILE_BYTES)      // 36864
#define NSTAGE 4
#define GEMM_SMEM_BYTES (NSTAGE * STAGE_BYTES)   // 147456

__global__ __launch_bounds__(256, 1) void gemm_f16(
    const __half* __restrict__ A, const __half* __restrict__ Wbase,
    float* __restrict__ C0, float* __restrict__ C1, float* __restrict__ C2,
    int M, int N, int K)
{
    extern __shared__ __half smem[];

    const int tid  = threadIdx.x;
    const int wid  = tid >> 5;
    const int lane = tid & 31;
    const int rowBase = blockIdx.y * GM;
    const int colBase = blockIdx.x * GN;
    const int z = blockIdx.z;

    const __half* Bw = Wbase + (size_t)z * D_MODEL * D_MODEL;
    float* C = (z == 0) ? C0 : (z == 1) ? C1 : C2;

    const int wm = (wid >> 2) * 64;
    const int wn = (wid & 3) * 32;

    const uint32_t smBase = smem_u32(smem);

    float acc[4][4][4];
#pragma unroll
    for (int i = 0; i < 4; i++)
#pragma unroll
        for (int j = 0; j < 4; j++)
#pragma unroll
            for (int c = 0; c < 4; c++) acc[i][j][c] = 0.0f;

    const int aRow = lane & 15;
    const int aKo  = (lane >> 4) * 8;
    const int bNo  = ((lane >> 4) << 3) + (lane & 7);
    const int bKo  = ((lane >> 3) & 1) * 8;

    const int NCH = K / GKC;              // 16

    auto issue = [&](int ci) {
        const int k0 = ci * GKC;
        const uint32_t stage = smBase + (uint32_t)(ci % NSTAGE) * STAGE_BYTES;
#pragma unroll
        for (int i = 0; i < 4; i++) {
            int L = tid + (i << 8);
            int row = L >> 3;
            int seg = L & 7;
            uint32_t off = (uint32_t)row * (AST * 2) + seg * 16;
            cp_async16(stage + off,
                       A + (size_t)(rowBase + row) * K + k0 + seg * 8);
            cp_async16(stage + TILE_BYTES + off,
                       Bw + (size_t)(colBase + row) * K + k0 + seg * 8);
        }
        CP_COMMIT();
    };

    issue(0);
    issue(1);
    issue(2);

    for (int ci = 0; ci < NCH; ci++) {
        CP_WAIT(2);
        __syncthreads();
        if (ci + 3 < NCH) issue(ci + 3);
        else CP_COMMIT();

        const uint32_t stage  = smBase + (uint32_t)(ci % NSTAGE) * STAGE_BYTES;
        const uint32_t bBase0 = stage + TILE_BYTES;

#pragma unroll
        for (int ks = 0; ks < 4; ks++) {
            uint32_t Ar[4][4];
#pragma unroll
            for (int mi = 0; mi < 4; mi++) {
                uint32_t addr = stage + (uint32_t)(wm + mi * 16 + aRow) * (AST * 2)
                              + (uint32_t)(ks * 16 + aKo) * 2;
                ldsm_x4(Ar[mi], addr);
            }
            uint32_t Br[2][4];
#pragma unroll
            for (int ni = 0; ni < 2; ni++) {
                uint32_t addr = bBase0 + (uint32_t)(wn + ni * 16 + bNo) * (AST * 2)
                              + (uint32_t)(ks * 16 + bKo) * 2;
                ldsm_x4(Br[ni], addr);
            }
#pragma unroll
            for (int mi = 0; mi < 4; mi++)
#pragma unroll
                for (int j = 0; j < 4; j++)
                    mma_16816_f16(acc[mi][j], Ar[mi],
                                  Br[j >> 1][(j & 1) * 2], Br[j >> 1][(j & 1) * 2 + 1]);
        }
    }

#pragma unroll
    for (int mi = 0; mi < 4; mi++) {
        const int row0 = rowBase + wm + mi * 16 + (lane >> 2);
#pragma unroll
        for (int j = 0; j < 4; j++) {
            const int col = colBase + wn + j * 8 + (lane & 3) * 2;
            *reinterpret_cast<float2*>(C + (size_t)row0 * N + col) =
                make_float2(acc[mi][j][0], acc[mi][j][1]);
            *reinterpret_cast<float2*>(C + (size_t)(row0 + 8) * N + col) =
                make_float2(acc[mi][j][2], acc[mi][j][3]);
        }
    }
}

// ---------------------------------------------------------------------------
// Fused x->fp16 convert + alpha (R8). Block = 16 rows, 512 threads.
// ---------------------------------------------------------------------------
__global__ __launch_bounds__(512) void cvtx_alpha_kernel(
    const float* __restrict__ x, const float* __restrict__ Wa,
    const float* __restrict__ ba, const float* __restrict__ m_gate,
    const float* __restrict__ ascale,
    __half* __restrict__ xh, float* __restrict__ alpha)
{
    extern __shared__ float xs[];        // [16][1024]
    const int tid  = threadIdx.x;
    const int warp = tid >> 5;
    const int lane = tid & 31;
    const int rowBase = blockIdx.x * 16;

    const float4* xg = reinterpret_cast<const float4*>(x + (size_t)rowBase * D_MODEL);
#pragma unroll
    for (int it = 0; it < 8; it++) {
        int i = tid + it * 512;
        float4 v = xg[i];
        reinterpret_cast<float4*>(xs)[i] = v;
        __half2* ph = reinterpret_cast<__half2*>(xh + (size_t)rowBase * D_MODEL + i * 4);
        ph[0] = __half2(__float2half_rn(v.x), __float2half_rn(v.y));
        ph[1] = __half2(__float2half_rn(v.z), __float2half_rn(v.w));
    }
    __syncthreads();

    float wa[32];
#pragma unroll
    for (int i = 0; i < 32; i++)
        wa[i] = Wa[(size_t)warp * D_MODEL + i * 32 + lane];
    const float bw = ba[warp];

#pragma unroll 4
    for (int row = 0; row < 16; row++) {
        const float* xr = xs + row * D_MODEL;
        float s = 0.0f;
#pragma unroll
        for (int i = 0; i < 32; i++)
            s = fmaf(wa[i], xr[i * 32 + lane], s);
#pragma unroll
        for (int off = 16; off; off >>= 1)
            s += __shfl_xor_sync(0xFFFFFFFFu, s, off);
        if (lane == 0) {
            const int r = rowBase + row;
            float sg = __fdividef(1.0f, 1.0f + __expf(-(s + bw)));
            float a = sg * m_gate[r] * ascale[(size_t)r * N_HEADS + warp];
            alpha[(size_t)r * N_HEADS + warp] = fminf(a, ALPHA_MAX);
        }
    }
}

// ---------------------------------------------------------------------------
// Round all 4 weight matrices to fp16 in one launch.
// ---------------------------------------------------------------------------
__global__ __launch_bounds__(256) void cvt4_kernel(
    const float* __restrict__ W0, const float* __restrict__ W1,
    const float* __restrict__ W2, const float* __restrict__ W3,
    __half* __restrict__ out)
{
    const int i = blockIdx.x * 256 + threadIdx.x;
    const int sel = i >> 20;
    const int off = i & ((1 << 20) - 1);
    const float* src = (sel == 0) ? W0 : (sel == 1) ? W1 : (sel == 2) ? W2 : W3;
    out[i] = __float2half_rn(src[off]);
}

// ---------------------------------------------------------------------------
// Sequential fast-weight scan (R11 structure, packed f32x2 arithmetic).
// Block = (b,h); 64 threads (thread = d); cp.async staging; 1 barrier/step;
// scores/y deferred one step.  State held as 8 packed (r,r+1) pairs each
// for U and V; decay, p-partials, fma updates, kf use f32x2 ops.
// ---------------------------------------------------------------------------
#define SCH 16   // timesteps per staging chunk

__global__ __launch_bounds__(64) void scan_kernel(
    const float* __restrict__ q, const float* __restrict__ k,
    const float* __restrict__ v, const float* __restrict__ alpha,
    __half* __restrict__ yh, int T)
{
    const int bh = blockIdx.x;
    const int b = bh / N_HEADS;
    const int h = bh % N_HEADS;
    const int d = threadIdx.x;
    const int warp = d >> 5;
    const int lane = d & 31;

    __shared__ float sq[2][SCH][D_HEAD];
    __shared__ float sk[2][SCH][D_HEAD];
    __shared__ float sv[2][SCH][D_HEAD];
    __shared__ float sa[2][SCH];
    __shared__ __align__(16) float sm_ku[2][2][16];  // [buf][warp][r]
    __shared__ float2 sm_sc[2][2];                   // [buf][warp]

    const uint32_t sq_a = smem_u32(sq);
    const uint32_t sk_a = smem_u32(sk);
    const uint32_t sv_a = smem_u32(sv);
    const uint32_t sa_a = smem_u32(sa);

    // packed state: pair i holds (r=2i, r=2i+1)
    u64t UP[8], VP[8];
    const u64t Z2 = pack2(0.0f, 0.0f);
#pragma unroll
    for (int i = 0; i < 8; i++) { UP[i] = Z2; VP[i] = Z2; }
    const u64t DEC2   = pack2(DECAY, DECAY);
    const u64t NBETA2 = pack2(-BETA, -BETA);

    const int l4 = lane & 15;
    const int rIdx = ((l4 & 1) << 3) | ((l4 & 2) << 1) | ((l4 & 4) >> 1) | ((l4 & 8) >> 3);

    const size_t strideT = (size_t)N_HEADS * D_HEAD;   // 1024
    const size_t qbase = (size_t)b * T * strideT + (size_t)h * D_HEAD;
    const size_t abase = (size_t)b * T * N_HEADS + h;

    auto issue = [&](int c) {
        const int t0 = c * SCH;
        const uint32_t bufB = (uint32_t)(c & 1) * (SCH * D_HEAD * 4);
#pragma unroll
        for (int i = 0; i < 4; i++) {
            int L = d + (i << 6);            // 0..255
            int s = L >> 4;
            int seg = L & 15;
            const size_t g = qbase + (size_t)(t0 + s) * strideT + seg * 4;
            const uint32_t so = bufB + (uint32_t)s * (D_HEAD * 4) + seg * 16;
            cp_async16(sq_a + so, q + g);
            cp_async16(sk_a + so, k + g);
            cp_async16(sv_a + so, v + g);
        }
        if (d < SCH)
            cp_async4(sa_a + (uint32_t)(c & 1) * (SCH * 4) + d * 4,
                      alpha + abase + (size_t)(t0 + d) * N_HEADS);
        CP_COMMIT();
    };

    issue(0);
    issue(1);

    float sp0 = 0.f, sp1 = 0.f;
    float vprev = 0.f, kfprev = 0.f;
    size_t yidxprev = 0;
    const int NCHK = T / SCH;               // 128

    for (int c = 0; c < NCHK; c++) {
        CP_WAIT(1);
        __syncthreads();
        const int buf = c & 1;
        const int t0 = c * SCH;

        float qt = sq[buf][0][d];
        float kt = sk[buf][0][d];
        float vt = sv[buf][0][d];
        float a  = sa[buf][0];

#pragma unroll 4
        for (int s = 0; s < SCH; s++) {
            const int t = t0 + s;
            const int pbuf = t & 1;

            float nq = 0.f, nk = 0.f, nv = 0.f, na = 0.f;
            if (s + 1 < SCH) {
                nq = sq[buf][s + 1][d];
                nk = sk[buf][s + 1][d];
                nv = sv[buf][s + 1][d];
                na = sa[buf][s + 1];
            }

            const float ktd = kt * DECAY;
            const u64t KTD2 = pack2(ktd, ktd);
            float p[RANK];
#pragma unroll
            for (int i = 0; i < 8; i++) {
                u64t pp = mul2(KTD2, UP[i]);
                unpack2(pp, p[2 * i], p[2 * i + 1]);
            }

#pragma unroll
            for (int st = 1, cnt = 8; st <= 8; st <<= 1, cnt >>= 1) {
                const bool hi = (lane & st) != 0;
#pragma unroll
                for (int i = 0; i < cnt; i++) {
                    float lo_v = p[i], hi_v = p[i + cnt];
                    float send = hi ? lo_v : hi_v;
                    float recv = __shfl_xor_sync(0xFFFFFFFFu, send, st);
                    p[i] = (hi ? hi_v : lo_v) + recv;
                }
            }
            float vr = p[0] + __shfl_xor_sync(0xFFFFFFFFu, p[0], 16);

            // decay (packed) overlaps the tree
#pragma unroll
            for (int i = 0; i < 8; i++) {
                UP[i] = mul2(DEC2, UP[i]);
                VP[i] = mul2(DEC2, VP[i]);
            }

            sm_ku[pbuf][warp][rIdx] = vr;
            if (lane == 0) sm_sc[pbuf][warp] = make_float2(sp0, sp1);
            __syncthreads();

            const float ak = a * kt;
            const float av = a * vt;
            const u64t AK2 = pack2(ak, ak);
            const u64t AV2 = pack2(av, av);
            u64t KF2 = Z2;
#pragma unroll
            for (int i = 0; i < 8; i++) {
                u64t ku2 = add2(*reinterpret_cast<const u64t*>(&sm_ku[pbuf][0][2 * i]),
                                *reinterpret_cast<const u64t*>(&sm_ku[pbuf][1][2 * i]));
                u64t u2 = fma2(AK2, ku2, UP[i]);
                u64t w2 = fma2(AV2, ku2, VP[i]);
                float ul, uh, wl, wh;
                unpack2(u2, ul, uh);
                unpack2(w2, wl, wh);
                const u64t cu2 = pack2(fminf(fmaxf(ul, -1.0f), 1.0f),
                                       fminf(fmaxf(uh, -1.0f), 1.0f));
                const u64t cw2 = pack2(fminf(fmaxf(wl, -1.0f), 1.0f),
                                       fminf(fmaxf(wh, -1.0f), 1.0f));
                u2 = fma2(NBETA2, cu2, u2);
                w2 = fma2(NBETA2, cw2, w2);
                UP[i] = u2;
                VP[i] = w2;
                KF2 = fma2(u2, w2, KF2);
            }
            float kfl, kfh;
            unpack2(KF2, kfl, kfh);
            const float kf = kfl + kfh;

            if (t > 0) {
                float2 w0 = sm_sc[pbuf][0];
                float2 w1 = sm_sc[pbuf][1];
                const float S0 = w0.x + w1.x;
                const float S1 = w0.y + w1.y;
                const float m1 = __fdividef(1.0f, 1.0f + __expf(S0 - S1));
                yh[yidxprev] = __float2half_rn((1.0f - m1) * vprev + m1 * kfprev);
            }

            const float qn = qt * 0.125f;
            float s0 = qn * kt;
            float s1 = qn * kf;
#pragma unroll
            for (int off = 16; off; off >>= 1) {
                s0 += __shfl_xor_sync(0xFFFFFFFFu, s0, off);
                s1 += __shfl_xor_sync(0xFFFFFFFFu, s1, off);
            }
            sp0 = s0; sp1 = s1;
            vprev = vt; kfprev = kf;
            yidxprev = qbase + (size_t)t * strideT + d;

            qt = nq; kt = nk; vt = nv; a = na;
        }

        __syncthreads();
        if (c + 2 < NCHK) issue(c + 2);
        else CP_COMMIT();
    }

    if (lane == 0) sm_sc[T & 1][warp] = make_float2(sp0, sp1);
    __syncthreads();
    {
        float2 w0 = sm_sc[T & 1][0];
        float2 w1 = sm_sc[T & 1][1];
        const float S0 = w0.x + w1.x;
        const float S1 = w0.y + w1.y;
        const float m1 = __fdividef(1.0f, 1.0f + __expf(S0 - S1));
        yh[yidxprev] = __float2half_rn((1.0f - m1) * vprev + m1 * kfprev);
    }
}

// ---------------------------------------------------------------------------
// Launch (single stream, R11 sequence)
// ---------------------------------------------------------------------------
extern "C" void kernel_launch(void* const* d_in, const int* in_sizes, int n_in,
                              void* d_out, int out_size)
{
    const float* x      = (const float*)d_in[0];
    const float* m_gate = (const float*)d_in[1];
    const float* ascale = (const float*)d_in[2];
    const float* Wq     = (const float*)d_in[3];
    const float* Wk     = (const float*)d_in[4];
    const float* Wv     = (const float*)d_in[5];
    const float* Wo     = (const float*)d_in[6];
    const float* Wa     = (const float*)d_in[7];
    const float* ba     = (const float*)d_in[8];
    // d_in[9] = mix_logit: cancels in the 2-way softmax; unused.
    float* out = (float*)d_out;

    const int M = in_sizes[1] > 0 ? in_sizes[1] : BT;  // B*T
    const int T = M / BB;

    __half *xh, *wf, *yh;
    float *dq, *dk, *dv, *da;
    cudaGetSymbolAddress((void**)&xh, g_xh);
    cudaGetSymbolAddress((void**)&wf, g_w);
    cudaGetSymbolAddress((void**)&yh, g_yh);
    cudaGetSymbolAddress((void**)&dq, g_q);
    cudaGetSymbolAddress((void**)&dk, g_k);
    cudaGetSymbolAddress((void**)&dv, g_v);
    cudaGetSymbolAddress((void**)&da, g_alpha);

    const int DW = D_MODEL * D_MODEL;

    static bool attr_set = false;
    if (!attr_set) {
        cudaFuncSetAttribute(gemm_f16,
                             cudaFuncAttributeMaxDynamicSharedMemorySize, GEMM_SMEM_BYTES);
        cudaFuncSetAttribute(cvtx_alpha_kernel,
                             cudaFuncAttributeMaxDynamicSharedMemorySize, 16 * D_MODEL * 4);
        attr_set = true;
    }

    cvtx_alpha_kernel<<<M / 16, 512, 16 * D_MODEL * 4>>>(
        x, Wa, ba, m_gate, ascale, xh, da);

    cvt4_kernel<<<(4 * DW) / 256, 256>>>(Wq, Wk, Wv, Wo, wf);

    dim3 gqkv(D_MODEL / GN, M / GM, 3);
    gemm_f16<<<gqkv, 256, GEMM_SMEM_BYTES>>>(xh, wf, dq, dk, dv, M, D_MODEL, D_MODEL);

    scan_kernel<<<BB * N_HEADS, 64>>>(dq, dk, dv, da, yh, T);

    dim3 go(D_MODEL / GN, M / GM, 1);
    gemm_f16<<<go, 256, GEMM_SMEM_BYTES>>>(yh, wf + (size_t)3 * DW,
                                           out, out, out, M, D_MODEL, D_MODEL);
}

// round 15
// speedup vs baseline: 1.3265x; 1.0439x over previous
#include <cuda_runtime.h>
#include <cuda_fp16.h>
#include <math.h>
#include <stdint.h>

// ---------------------------------------------------------------------------
// CortexBlock on GB300 (compute_103 pipeline => mma.sync HMMA path)
// B=4, T=2048, D=1024, H=16, Dh=64, R=16
// R14 GEMMs + slim scan (state recurrence only -> kf), with scores/softmax/mix
// evicted to a fully parallel epilogue kernel (q/k/v/kf -> yh).
// ---------------------------------------------------------------------------

#define D_MODEL 1024
#define N_HEADS 16
#define D_HEAD  64
#define RANK    16
#define DECAY   0.95f
#define ALPHA_MAX 0.05f
#define BETA    0.01f

#define BB 4
#define TT 2048
#define BT (BB*TT)   // 8192

// ---------------- scratch (static device globals; no allocs allowed) -------
__device__ __align__(256) __half g_xh[BT * D_MODEL];
__device__ __align__(256) __half g_w[4 * D_MODEL * D_MODEL];   // Wq,Wk,Wv,Wo fp16
__device__ __align__(256) __half g_yh[BT * D_MODEL];
__device__ __align__(256) float g_q[BT * D_MODEL];
__device__ __align__(256) float g_k[BT * D_MODEL];
__device__ __align__(256) float g_v[BT * D_MODEL];
__device__ __align__(256) float g_kf[BT * D_MODEL];
__device__ __align__(256) float g_alpha[BT * N_HEADS];

// ---------------- small asm helpers ----------------------------------------
typedef unsigned long long u64t;
__device__ __forceinline__ u64t pack2(float lo, float hi) {
    u64t r; asm("mov.b64 %0, {%1, %2};" : "=l"(r) : "f"(lo), "f"(hi)); return r;
}
__device__ __forceinline__ void unpack2(u64t p, float& lo, float& hi) {
    asm("mov.b64 {%0, %1}, %2;" : "=f"(lo), "=f"(hi) : "l"(p));
}
__device__ __forceinline__ u64t fma2(u64t a, u64t b, u64t c) {
    u64t d; asm("fma.rn.f32x2 %0, %1, %2, %3;" : "=l"(d) : "l"(a), "l"(b), "l"(c)); return d;
}
__device__ __forceinline__ u64t mul2(u64t a, u64t b) {
    u64t d; asm("mul.rn.f32x2 %0, %1, %2;" : "=l"(d) : "l"(a), "l"(b)); return d;
}
__device__ __forceinline__ u64t add2(u64t a, u64t b) {
    u64t d; asm("add.rn.f32x2 %0, %1, %2;" : "=l"(d) : "l"(a), "l"(b)); return d;
}

__device__ __forceinline__ uint32_t smem_u32(const void* p) {
    uint32_t a;
    asm("{ .reg .u64 t; cvta.to.shared.u64 t, %1; cvt.u32.u64 %0, t; }"
        : "=r"(a) : "l"(p));
    return a;
}
__device__ __forceinline__ void cp_async16(uint32_t daddr, const void* gaddr) {
    asm volatile("cp.async.cg.shared.global [%0], [%1], 16;"
                 :: "r"(daddr), "l"(gaddr) : "memory");
}
__device__ __forceinline__ void cp_async4(uint32_t daddr, const void* gaddr) {
    asm volatile("cp.async.ca.shared.global [%0], [%1], 4;"
                 :: "r"(daddr), "l"(gaddr) : "memory");
}
#define CP_COMMIT()  asm volatile("cp.async.commit_group;" ::: "memory")
#define CP_WAIT(n)   asm volatile("cp.async.wait_group %0;" :: "n"(n) : "memory")

__device__ __forceinline__ void ldsm_x4(uint32_t (&r)[4], uint32_t addr) {
    asm volatile("ldmatrix.sync.aligned.m8n8.x4.shared.b16 {%0,%1,%2,%3}, [%4];"
                 : "=r"(r[0]), "=r"(r[1]), "=r"(r[2]), "=r"(r[3]) : "r"(addr));
}
__device__ __forceinline__ void mma_16816_f16(float (&d)[4], const uint32_t (&a)[4],
                                              uint32_t b0, uint32_t b1) {
    asm volatile(
        "mma.sync.aligned.m16n8k16.row.col.f32.f16.f16.f32 "
        "{%0,%1,%2,%3}, {%4,%5,%6,%7}, {%8,%9}, {%0,%1,%2,%3};"
        : "+f"(d[0]), "+f"(d[1]), "+f"(d[2]), "+f"(d[3])
        : "r"(a[0]), "r"(a[1]), "r"(a[2]), "r"(a[3]), "r"(b0), "r"(b1));
}

// ---------------------------------------------------------------------------
// fp16 single-pass GEMM (R8 config): C[M,N](fp32) = A[M,K] * W[N,K]^T
// CTA tile 128x128, K-chunk 64, 4-stage cp.async, 1 barrier/chunk.
// ---------------------------------------------------------------------------
#define GM 128
#define GN 128
#define GKC 64
#define AST 72
#define TILE_HALVES (GM * AST)            // 9216 halves = 18432 B
#define TILE_BYTES  (TILE_HALVES * 2)
#define STAGE_BYTES (2 * TILE_BYTES)      // 36864
#define NSTAGE 4
#define GEMM_SMEM_BYTES (NSTAGE * STAGE_BYTES)   // 147456

__global__ __launch_bounds__(256, 1) void gemm_f16(
    const __half* __restrict__ A, const __half* __restrict__ Wbase,
    float* __restrict__ C0, float* __restrict__ C1, float* __restrict__ C2,
    int M, int N, int K)
{
    extern __shared__ __half smem[];

    const int tid  = threadIdx.x;
    const int wid  = tid >> 5;
    const int lane = tid & 31;
    const int rowBase = blockIdx.y * GM;
    const int colBase = blockIdx.x * GN;
    const int z = blockIdx.z;

    const __half* Bw = Wbase + (size_t)z * D_MODEL * D_MODEL;
    float* C = (z == 0) ? C0 : (z == 1) ? C1 : C2;

    const int wm = (wid >> 2) * 64;
    const int wn = (wid & 3) * 32;

    const uint32_t smBase = smem_u32(smem);

    float acc[4][4][4];
#pragma unroll
    for (int i = 0; i < 4; i++)
#pragma unroll
        for (int j = 0; j < 4; j++)
#pragma unroll
            for (int c = 0; c < 4; c++) acc[i][j][c] = 0.0f;

    const int aRow = lane & 15;
    const int aKo  = (lane >> 4) * 8;
    const int bNo  = ((lane >> 4) << 3) + (lane & 7);
    const int bKo  = ((lane >> 3) & 1) * 8;

    const int NCH = K / GKC;              // 16

    auto issue = [&](int ci) {
        const int k0 = ci * GKC;
        const uint32_t stage = smBase + (uint32_t)(ci % NSTAGE) * STAGE_BYTES;
#pragma unroll
        for (int i = 0; i < 4; i++) {
            int L = tid + (i << 8);
            int row = L >> 3;
            int seg = L & 7;
            uint32_t off = (uint32_t)row * (AST * 2) + seg * 16;
            cp_async16(stage + off,
                       A + (size_t)(rowBase + row) * K + k0 + seg * 8);
            cp_async16(stage + TILE_BYTES + off,
                       Bw + (size_t)(colBase + row) * K + k0 + seg * 8);
        }
        CP_COMMIT();
    };

    issue(0);
    issue(1);
    issue(2);

    for (int ci = 0; ci < NCH; ci++) {
        CP_WAIT(2);
        __syncthreads();
        if (ci + 3 < NCH) issue(ci + 3);
        else CP_COMMIT();

        const uint32_t stage  = smBase + (uint32_t)(ci % NSTAGE) * STAGE_BYTES;
        const uint32_t bBase0 = stage + TILE_BYTES;

#pragma unroll
        for (int ks = 0; ks < 4; ks++) {
            uint32_t Ar[4][4];
#pragma unroll
            for (int mi = 0; mi < 4; mi++) {
                uint32_t addr = stage + (uint32_t)(wm + mi * 16 + aRow) * (AST * 2)
                              + (uint32_t)(ks * 16 + aKo) * 2;
                ldsm_x4(Ar[mi], addr);
            }
            uint32_t Br[2][4];
#pragma unroll
            for (int ni = 0; ni < 2; ni++) {
                uint32_t addr = bBase0 + (uint32_t)(wn + ni * 16 + bNo) * (AST * 2)
                              + (uint32_t)(ks * 16 + bKo) * 2;
                ldsm_x4(Br[ni], addr);
            }
#pragma unroll
            for (int mi = 0; mi < 4; mi++)
#pragma unroll
                for (int j = 0; j < 4; j++)
                    mma_16816_f16(acc[mi][j], Ar[mi],
                                  Br[j >> 1][(j & 1) * 2], Br[j >> 1][(j & 1) * 2 + 1]);
        }
    }

#pragma unroll
    for (int mi = 0; mi < 4; mi++) {
        const int row0 = rowBase + wm + mi * 16 + (lane >> 2);
#pragma unroll
        for (int j = 0; j < 4; j++) {
            const int col = colBase + wn + j * 8 + (lane & 3) * 2;
            *reinterpret_cast<float2*>(C + (size_t)row0 * N + col) =
                make_float2(acc[mi][j][0], acc[mi][j][1]);
            *reinterpret_cast<float2*>(C + (size_t)(row0 + 8) * N + col) =
                make_float2(acc[mi][j][2], acc[mi][j][3]);
        }
    }
}

// ---------------------------------------------------------------------------
// Fused x->fp16 convert + alpha. Block = 16 rows, 512 threads.
// ---------------------------------------------------------------------------
__global__ __launch_bounds__(512) void cvtx_alpha_kernel(
    const float* __restrict__ x, const float* __restrict__ Wa,
    const float* __restrict__ ba, const float* __restrict__ m_gate,
    const float* __restrict__ ascale,
    __half* __restrict__ xh, float* __restrict__ alpha)
{
    extern __shared__ float xs[];        // [16][1024]
    const int tid  = threadIdx.x;
    const int warp = tid >> 5;
    const int lane = tid & 31;
    const int rowBase = blockIdx.x * 16;

    const float4* xg = reinterpret_cast<const float4*>(x + (size_t)rowBase * D_MODEL);
#pragma unroll
    for (int it = 0; it < 8; it++) {
        int i = tid + it * 512;
        float4 v = xg[i];
        reinterpret_cast<float4*>(xs)[i] = v;
        __half2* ph = reinterpret_cast<__half2*>(xh + (size_t)rowBase * D_MODEL + i * 4);
        ph[0] = __half2(__float2half_rn(v.x), __float2half_rn(v.y));
        ph[1] = __half2(__float2half_rn(v.z), __float2half_rn(v.w));
    }
    __syncthreads();

    float wa[32];
#pragma unroll
    for (int i = 0; i < 32; i++)
        wa[i] = Wa[(size_t)warp * D_MODEL + i * 32 + lane];
    const float bw = ba[warp];

#pragma unroll 4
    for (int row = 0; row < 16; row++) {
        const float* xr = xs + row * D_MODEL;
        float s = 0.0f;
#pragma unroll
        for (int i = 0; i < 32; i++)
            s = fmaf(wa[i], xr[i * 32 + lane], s);
#pragma unroll
        for (int off = 16; off; off >>= 1)
            s += __shfl_xor_sync(0xFFFFFFFFu, s, off);
        if (lane == 0) {
            const int r = rowBase + row;
            float sg = __fdividef(1.0f, 1.0f + __expf(-(s + bw)));
            float a = sg * m_gate[r] * ascale[(size_t)r * N_HEADS + warp];
            alpha[(size_t)r * N_HEADS + warp] = fminf(a, ALPHA_MAX);
        }
    }
}

// ---------------------------------------------------------------------------
// Round all 4 weight matrices to fp16 in one launch.
// ---------------------------------------------------------------------------
__global__ __launch_bounds__(256) void cvt4_kernel(
    const float* __restrict__ W0, const float* __restrict__ W1,
    const float* __restrict__ W2, const float* __restrict__ W3,
    __half* __restrict__ out)
{
    const int i = blockIdx.x * 256 + threadIdx.x;
    const int sel = i >> 20;
    const int off = i & ((1 << 20) - 1);
    const float* src = (sel == 0) ? W0 : (sel == 1) ? W1 : (sel == 2) ? W2 : W3;
    out[i] = __float2half_rn(src[off]);
}

// ---------------------------------------------------------------------------
// Slim sequential fast-weight scan: state recurrence only; emits kf (fp32).
// Block = (b,h); 64 threads (thread = d). cp.async staging of k/v/alpha.
// Packed f32x2 state math (R14). One barrier per step (sm_ku double buffer).
// No q, no scores, no softmax, no y: all moved to mix_kernel.
// ---------------------------------------------------------------------------
#define SCH 16   // timesteps per staging chunk

__global__ __launch_bounds__(64) void scan_kernel(
    const float* __restrict__ k, const float* __restrict__ v,
    const float* __restrict__ alpha, float* __restrict__ kf_out, int T)
{
    const int bh = blockIdx.x;
    const int b = bh / N_HEADS;
    const int h = bh % N_HEADS;
    const int d = threadIdx.x;
    const int warp = d >> 5;
    const int lane = d & 31;

    __shared__ float sk[2][SCH][D_HEAD];
    __shared__ float sv[2][SCH][D_HEAD];
    __shared__ float sa[2][SCH];
    __shared__ __align__(16) float sm_ku[2][2][16];  // [buf][warp][r]

    const uint32_t sk_a = smem_u32(sk);
    const uint32_t sv_a = smem_u32(sv);
    const uint32_t sa_a = smem_u32(sa);

    u64t UP[8], VP[8];
    const u64t Z2 = pack2(0.0f, 0.0f);
#pragma unroll
    for (int i = 0; i < 8; i++) { UP[i] = Z2; VP[i] = Z2; }
    const u64t DEC2   = pack2(DECAY, DECAY);
    const u64t NBETA2 = pack2(-BETA, -BETA);

    const int l4 = lane & 15;
    const int rIdx = ((l4 & 1) << 3) | ((l4 & 2) << 1) | ((l4 & 4) >> 1) | ((l4 & 8) >> 3);

    const size_t strideT = (size_t)N_HEADS * D_HEAD;   // 1024
    const size_t kbase = (size_t)b * T * strideT + (size_t)h * D_HEAD;
    const size_t abase = (size_t)b * T * N_HEADS + h;

    auto issue = [&](int c) {
        const int t0 = c * SCH;
        const uint32_t bufB = (uint32_t)(c & 1) * (SCH * D_HEAD * 4);
#pragma unroll
        for (int i = 0; i < 4; i++) {
            int L = d + (i << 6);            // 0..255
            int s = L >> 4;
            int seg = L & 15;
            const size_t g = kbase + (size_t)(t0 + s) * strideT + seg * 4;
            const uint32_t so = bufB + (uint32_t)s * (D_HEAD * 4) + seg * 16;
            cp_async16(sk_a + so, k + g);
            cp_async16(sv_a + so, v + g);
        }
        if (d < SCH)
            cp_async4(sa_a + (uint32_t)(c & 1) * (SCH * 4) + d * 4,
                      alpha + abase + (size_t)(t0 + d) * N_HEADS);
        CP_COMMIT();
    };

    issue(0);
    issue(1);

    const int NCHK = T / SCH;               // 128

    for (int c = 0; c < NCHK; c++) {
        CP_WAIT(1);
        __syncthreads();
        const int buf = c & 1;
        const int t0 = c * SCH;

        float kt = sk[buf][0][d];
        float vt = sv[buf][0][d];
        float a  = sa[buf][0];

#pragma unroll 4
        for (int s = 0; s < SCH; s++) {
            const int t = t0 + s;
            const int pbuf = t & 1;

            float nk = 0.f, nv = 0.f, na = 0.f;
            if (s + 1 < SCH) {
                nk = sk[buf][s + 1][d];
                nv = sv[buf][s + 1][d];
                na = sa[buf][s + 1];
            }

            const float ktd = kt * DECAY;
            const u64t KTD2 = pack2(ktd, ktd);
            float p[RANK];
#pragma unroll
            for (int i = 0; i < 8; i++) {
                u64t pp = mul2(KTD2, UP[i]);
                unpack2(pp, p[2 * i], p[2 * i + 1]);
            }

#pragma unroll
            for (int st = 1, cnt = 8; st <= 8; st <<= 1, cnt >>= 1) {
                const bool hi = (lane & st) != 0;
#pragma unroll
                for (int i = 0; i < cnt; i++) {
                    float lo_v = p[i], hi_v = p[i + cnt];
                    float send = hi ? lo_v : hi_v;
                    float recv = __shfl_xor_sync(0xFFFFFFFFu, send, st);
                    p[i] = (hi ? hi_v : lo_v) + recv;
                }
            }
            float vr = p[0] + __shfl_xor_sync(0xFFFFFFFFu, p[0], 16);

            // decay (packed) overlaps the tree
#pragma unroll
            for (int i = 0; i < 8; i++) {
                UP[i] = mul2(DEC2, UP[i]);
                VP[i] = mul2(DEC2, VP[i]);
            }

            sm_ku[pbuf][warp][rIdx] = vr;
            __syncthreads();

            const float ak = a * kt;
            const float av = a * vt;
            const u64t AK2 = pack2(ak, ak);
            const u64t AV2 = pack2(av, av);
            u64t KF2 = Z2;
#pragma unroll
            for (int i = 0; i < 8; i++) {
                u64t ku2 = add2(*reinterpret_cast<const u64t*>(&sm_ku[pbuf][0][2 * i]),
                                *reinterpret_cast<const u64t*>(&sm_ku[pbuf][1][2 * i]));
                u64t u2 = fma2(AK2, ku2, UP[i]);
                u64t w2 = fma2(AV2, ku2, VP[i]);
                float ul, uh, wl, wh;
                unpack2(u2, ul, uh);
                unpack2(w2, wl, wh);
                const u64t cu2 = pack2(fminf(fmaxf(ul, -1.0f), 1.0f),
                                       fminf(fmaxf(uh, -1.0f), 1.0f));
                const u64t cw2 = pack2(fminf(fmaxf(wl, -1.0f), 1.0f),
                                       fminf(fmaxf(wh, -1.0f), 1.0f));
                u2 = fma2(NBETA2, cu2, u2);
                w2 = fma2(NBETA2, cw2, w2);
                UP[i] = u2;
                VP[i] = w2;
                KF2 = fma2(u2, w2, KF2);
            }
            float kfl, kfh;
            unpack2(KF2, kfl, kfh);

            // emit kf (off the critical chain)
            kf_out[kbase + (size_t)t * strideT + d] = kfl + kfh;

            kt = nk; vt = nv; a = na;
        }

        __syncthreads();
        if (c + 2 < NCHK) issue(c + 2);
        else CP_COMMIT();
    }
}

// ---------------------------------------------------------------------------
// Parallel mix epilogue: per (b,t,h) compute s0=q.k/8, s1=q.kf/8, 2-way
// softmax, y = m0*v + m1*kf -> yh (fp16).  Block = one (b,t) row, 256 thr,
// 8 warps x 2 heads; lane owns d=lane, d=lane+32.
// ---------------------------------------------------------------------------
__global__ __launch_bounds__(256) void mix_kernel(
    const float* __restrict__ q, const float* __restrict__ k,
    const float* __restrict__ v, const float* __restrict__ kf,
    __half* __restrict__ yh)
{
    const int row = blockIdx.x;          // b*T + t
    const int warp = threadIdx.x >> 5;   // 0..7
    const int lane = threadIdx.x & 31;

#pragma unroll
    for (int hh = 0; hh < 2; hh++) {
        const int h = warp * 2 + hh;
        const size_t base = (size_t)row * D_MODEL + h * D_HEAD;
        const float q0 = q[base + lane],      q1 = q[base + lane + 32];
        const float k0 = k[base + lane],      k1 = k[base + lane + 32];
        const float f0 = kf[base + lane],     f1 = kf[base + lane + 32];

        float s0 = fmaf(q1, k1, q0 * k0);
        float s1 = fmaf(q1, f1, q0 * f0);
#pragma unroll
        for (int off = 16; off; off >>= 1) {
            s0 += __shfl_xor_sync(0xFFFFFFFFu, s0, off);
            s1 += __shfl_xor_sync(0xFFFFFFFFu, s1, off);
        }
        const float m1 = __fdividef(1.0f, 1.0f + __expf((s0 - s1) * 0.125f));
        const float m0 = 1.0f - m1;

        const float v0 = v[base + lane], v1 = v[base + lane + 32];
        yh[base + lane]      = __float2half_rn(m0 * v0 + m1 * f0);
        yh[base + lane + 32] = __float2half_rn(m0 * v1 + m1 * f1);
    }
}

// ---------------------------------------------------------------------------
// Launch (single stream)
// ---------------------------------------------------------------------------
extern "C" void kernel_launch(void* const* d_in, const int* in_sizes, int n_in,
                              void* d_out, int out_size)
{
    const float* x      = (const float*)d_in[0];
    const float* m_gate = (const float*)d_in[1];
    const float* ascale = (const float*)d_in[2];
    const float* Wq     = (const float*)d_in[3];
    const float* Wk     = (const float*)d_in[4];
    const float* Wv     = (const float*)d_in[5];
    const float* Wo     = (const float*)d_in[6];
    const float* Wa     = (const float*)d_in[7];
    const float* ba     = (const float*)d_in[8];
    // d_in[9] = mix_logit: cancels in the 2-way softmax; unused.
    float* out = (float*)d_out;

    const int M = in_sizes[1] > 0 ? in_sizes[1] : BT;  // B*T
    const int T = M / BB;

    __half *xh, *wf, *yh;
    float *dq, *dk, *dv, *dkf, *da;
    cudaGetSymbolAddress((void**)&xh, g_xh);
    cudaGetSymbolAddress((void**)&wf, g_w);
    cudaGetSymbolAddress((void**)&yh, g_yh);
    cudaGetSymbolAddress((void**)&dq, g_q);
    cudaGetSymbolAddress((void**)&dk, g_k);
    cudaGetSymbolAddress((void**)&dv, g_v);
    cudaGetSymbolAddress((void**)&dkf, g_kf);
    cudaGetSymbolAddress((void**)&da, g_alpha);

    const int DW = D_MODEL * D_MODEL;

    static bool attr_set = false;
    if (!attr_set) {
        cudaFuncSetAttribute(gemm_f16,
                             cudaFuncAttributeMaxDynamicSharedMemorySize, GEMM_SMEM_BYTES);
        cudaFuncSetAttribute(cvtx_alpha_kernel,
                             cudaFuncAttributeMaxDynamicSharedMemorySize, 16 * D_MODEL * 4);
        attr_set = true;
    }

    cvtx_alpha_kernel<<<M / 16, 512, 16 * D_MODEL * 4>>>(
        x, Wa, ba, m_gate, ascale, xh, da);

    cvt4_kernel<<<(4 * DW) / 256, 256>>>(Wq, Wk, Wv, Wo, wf);

    dim3 gqkv(D_MODEL / GN, M / GM, 3);
    gemm_f16<<<gqkv, 256, GEMM_SMEM_BYTES>>>(xh, wf, dq, dk, dv, M, D_MODEL, D_MODEL);

    scan_kernel<<<BB * N_HEADS, 64>>>(dk, dv, da, dkf, T);

    mix_kernel<<<M, 256>>>(dq, dk, dv, dkf, yh);

    dim3 go(D_MODEL / GN, M / GM, 1);
    gemm_f16<<<go, 256, GEMM_SMEM_BYTES>>>(yh, wf + (size_t)3 * DW,
                                           out, out, out, M, D_MODEL, D_MODEL);
}

// round 16
// speedup vs baseline: 2.0033x; 1.5102x over previous
#include <cuda_runtime.h>
#include <cuda_fp16.h>
#include <math.h>
#include <stdint.h>

// ---------------------------------------------------------------------------
// CortexBlock on GB300 (compute_103 pipeline => mma.sync HMMA path)
// B=4, T=2048, D=1024, H=16, Dh=64, R=16
// R15 pipeline + CHUNKED scan: 4 T-chunks in parallel, each warm-started
// 384 steps early with zero state (contractive recurrence => truncation
// error ~1e-5, far under the fp16 floor).
// ---------------------------------------------------------------------------

#define D_MODEL 1024
#define N_HEADS 16
#define D_HEAD  64
#define RANK    16
#define DECAY   0.95f
#define ALPHA_MAX 0.05f
#define BETA    0.01f

#define BB 4
#define TT 2048
#define BT (BB*TT)   // 8192
#define NSC 4        // scan chunks
#define BURN 384     // warm-up steps for chunks z>0

// ---------------- scratch (static device globals; no allocs allowed) -------
__device__ __align__(256) __half g_xh[BT * D_MODEL];
__device__ __align__(256) __half g_w[4 * D_MODEL * D_MODEL];   // Wq,Wk,Wv,Wo fp16
__device__ __align__(256) __half g_yh[BT * D_MODEL];
__device__ __align__(256) float g_q[BT * D_MODEL];
__device__ __align__(256) float g_k[BT * D_MODEL];
__device__ __align__(256) float g_v[BT * D_MODEL];
__device__ __align__(256) float g_kf[BT * D_MODEL];
__device__ __align__(256) float g_alpha[BT * N_HEADS];

// ---------------- small asm helpers ----------------------------------------
typedef unsigned long long u64t;
__device__ __forceinline__ u64t pack2(float lo, float hi) {
    u64t r; asm("mov.b64 %0, {%1, %2};" : "=l"(r) : "f"(lo), "f"(hi)); return r;
}
__device__ __forceinline__ void unpack2(u64t p, float& lo, float& hi) {
    asm("mov.b64 {%0, %1}, %2;" : "=f"(lo), "=f"(hi) : "l"(p));
}
__device__ __forceinline__ u64t fma2(u64t a, u64t b, u64t c) {
    u64t d; asm("fma.rn.f32x2 %0, %1, %2, %3;" : "=l"(d) : "l"(a), "l"(b), "l"(c)); return d;
}
__device__ __forceinline__ u64t mul2(u64t a, u64t b) {
    u64t d; asm("mul.rn.f32x2 %0, %1, %2;" : "=l"(d) : "l"(a), "l"(b)); return d;
}
__device__ __forceinline__ u64t add2(u64t a, u64t b) {
    u64t d; asm("add.rn.f32x2 %0, %1, %2;" : "=l"(d) : "l"(a), "l"(b)); return d;
}

__device__ __forceinline__ uint32_t smem_u32(const void* p) {
    uint32_t a;
    asm("{ .reg .u64 t; cvta.to.shared.u64 t, %1; cvt.u32.u64 %0, t; }"
        : "=r"(a) : "l"(p));
    return a;
}
__device__ __forceinline__ void cp_async16(uint32_t daddr, const void* gaddr) {
    asm volatile("cp.async.cg.shared.global [%0], [%1], 16;"
                 :: "r"(daddr), "l"(gaddr) : "memory");
}
__device__ __forceinline__ void cp_async4(uint32_t daddr, const void* gaddr) {
    asm volatile("cp.async.ca.shared.global [%0], [%1], 4;"
                 :: "r"(daddr), "l"(gaddr) : "memory");
}
#define CP_COMMIT()  asm volatile("cp.async.commit_group;" ::: "memory")
#define CP_WAIT(n)   asm volatile("cp.async.wait_group %0;" :: "n"(n) : "memory")

__device__ __forceinline__ void ldsm_x4(uint32_t (&r)[4], uint32_t addr) {
    asm volatile("ldmatrix.sync.aligned.m8n8.x4.shared.b16 {%0,%1,%2,%3}, [%4];"
                 : "=r"(r[0]), "=r"(r[1]), "=r"(r[2]), "=r"(r[3]) : "r"(addr));
}
__device__ __forceinline__ void mma_16816_f16(float (&d)[4], const uint32_t (&a)[4],
                                              uint32_t b0, uint32_t b1) {
    asm volatile(
        "mma.sync.aligned.m16n8k16.row.col.f32.f16.f16.f32 "
        "{%0,%1,%2,%3}, {%4,%5,%6,%7}, {%8,%9}, {%0,%1,%2,%3};"
        : "+f"(d[0]), "+f"(d[1]), "+f"(d[2]), "+f"(d[3])
        : "r"(a[0]), "r"(a[1]), "r"(a[2]), "r"(a[3]), "r"(b0), "r"(b1));
}

// ---------------------------------------------------------------------------
// fp16 single-pass GEMM (R8 config): C[M,N](fp32) = A[M,K] * W[N,K]^T
// ---------------------------------------------------------------------------
#define GM 128
#define GN 128
#define GKC 64
#define AST 72
#define TILE_HALVES (GM * AST)
#define TILE_BYTES  (TILE_HALVES * 2)
#define STAGE_BYTES (2 * TILE_BYTES)
#define NSTAGE 4
#define GEMM_SMEM_BYTES (NSTAGE * STAGE_BYTES)   // 147456

__global__ __launch_bounds__(256, 1) void gemm_f16(
    const __half* __restrict__ A, const __half* __restrict__ Wbase,
    float* __restrict__ C0, float* __restrict__ C1, float* __restrict__ C2,
    int M, int N, int K)
{
    extern __shared__ __half smem[];

    const int tid  = threadIdx.x;
    const int wid  = tid >> 5;
    const int lane = tid & 31;
    const int rowBase = blockIdx.y * GM;
    const int colBase = blockIdx.x * GN;
    const int z = blockIdx.z;

    const __half* Bw = Wbase + (size_t)z * D_MODEL * D_MODEL;
    float* C = (z == 0) ? C0 : (z == 1) ? C1 : C2;

    const int wm = (wid >> 2) * 64;
    const int wn = (wid & 3) * 32;

    const uint32_t smBase = smem_u32(smem);

    float acc[4][4][4];
#pragma unroll
    for (int i = 0; i < 4; i++)
#pragma unroll
        for (int j = 0; j < 4; j++)
#pragma unroll
            for (int c = 0; c < 4; c++) acc[i][j][c] = 0.0f;

    const int aRow = lane & 15;
    const int aKo  = (lane >> 4) * 8;
    const int bNo  = ((lane >> 4) << 3) + (lane & 7);
    const int bKo  = ((lane >> 3) & 1) * 8;

    const int NCH = K / GKC;

    auto issue = [&](int ci) {
        const int k0 = ci * GKC;
        const uint32_t stage = smBase + (uint32_t)(ci % NSTAGE) * STAGE_BYTES;
#pragma unroll
        for (int i = 0; i < 4; i++) {
            int L = tid + (i << 8);
            int row = L >> 3;
            int seg = L & 7;
            uint32_t off = (uint32_t)row * (AST * 2) + seg * 16;
            cp_async16(stage + off,
                       A + (size_t)(rowBase + row) * K + k0 + seg * 8);
            cp_async16(stage + TILE_BYTES + off,
                       Bw + (size_t)(colBase + row) * K + k0 + seg * 8);
        }
        CP_COMMIT();
    };

    issue(0);
    issue(1);
    issue(2);

    for (int ci = 0; ci < NCH; ci++) {
        CP_WAIT(2);
        __syncthreads();
        if (ci + 3 < NCH) issue(ci + 3);
        else CP_COMMIT();

        const uint32_t stage  = smBase + (uint32_t)(ci % NSTAGE) * STAGE_BYTES;
        const uint32_t bBase0 = stage + TILE_BYTES;

#pragma unroll
        for (int ks = 0; ks < 4; ks++) {
            uint32_t Ar[4][4];
#pragma unroll
            for (int mi = 0; mi < 4; mi++) {
                uint32_t addr = stage + (uint32_t)(wm + mi * 16 + aRow) * (AST * 2)
                              + (uint32_t)(ks * 16 + aKo) * 2;
                ldsm_x4(Ar[mi], addr);
            }
            uint32_t Br[2][4];
#pragma unroll
            for (int ni = 0; ni < 2; ni++) {
                uint32_t addr = bBase0 + (uint32_t)(wn + ni * 16 + bNo) * (AST * 2)
                              + (uint32_t)(ks * 16 + bKo) * 2;
                ldsm_x4(Br[ni], addr);
            }
#pragma unroll
            for (int mi = 0; mi < 4; mi++)
#pragma unroll
                for (int j = 0; j < 4; j++)
                    mma_16816_f16(acc[mi][j], Ar[mi],
                                  Br[j >> 1][(j & 1) * 2], Br[j >> 1][(j & 1) * 2 + 1]);
        }
    }

#pragma unroll
    for (int mi = 0; mi < 4; mi++) {
        const int row0 = rowBase + wm + mi * 16 + (lane >> 2);
#pragma unroll
        for (int j = 0; j < 4; j++) {
            const int col = colBase + wn + j * 8 + (lane & 3) * 2;
            *reinterpret_cast<float2*>(C + (size_t)row0 * N + col) =
                make_float2(acc[mi][j][0], acc[mi][j][1]);
            *reinterpret_cast<float2*>(C + (size_t)(row0 + 8) * N + col) =
                make_float2(acc[mi][j][2], acc[mi][j][3]);
        }
    }
}

// ---------------------------------------------------------------------------
// Fused x->fp16 convert + alpha. Block = 16 rows, 512 threads.
// ---------------------------------------------------------------------------
__global__ __launch_bounds__(512) void cvtx_alpha_kernel(
    const float* __restrict__ x, const float* __restrict__ Wa,
    const float* __restrict__ ba, const float* __restrict__ m_gate,
    const float* __restrict__ ascale,
    __half* __restrict__ xh, float* __restrict__ alpha)
{
    extern __shared__ float xs[];        // [16][1024]
    const int tid  = threadIdx.x;
    const int warp = tid >> 5;
    const int lane = tid & 31;
    const int rowBase = blockIdx.x * 16;

    const float4* xg = reinterpret_cast<const float4*>(x + (size_t)rowBase * D_MODEL);
#pragma unroll
    for (int it = 0; it < 8; it++) {
        int i = tid + it * 512;
        float4 v = xg[i];
        reinterpret_cast<float4*>(xs)[i] = v;
        __half2* ph = reinterpret_cast<__half2*>(xh + (size_t)rowBase * D_MODEL + i * 4);
        ph[0] = __half2(__float2half_rn(v.x), __float2half_rn(v.y));
        ph[1] = __half2(__float2half_rn(v.z), __float2half_rn(v.w));
    }
    __syncthreads();

    float wa[32];
#pragma unroll
    for (int i = 0; i < 32; i++)
        wa[i] = Wa[(size_t)warp * D_MODEL + i * 32 + lane];
    const float bw = ba[warp];

#pragma unroll 4
    for (int row = 0; row < 16; row++) {
        const float* xr = xs + row * D_MODEL;
        float s = 0.0f;
#pragma unroll
        for (int i = 0; i < 32; i++)
            s = fmaf(wa[i], xr[i * 32 + lane], s);
#pragma unroll
        for (int off = 16; off; off >>= 1)
            s += __shfl_xor_sync(0xFFFFFFFFu, s, off);
        if (lane == 0) {
            const int r = rowBase + row;
            float sg = __fdividef(1.0f, 1.0f + __expf(-(s + bw)));
            float a = sg * m_gate[r] * ascale[(size_t)r * N_HEADS + warp];
            alpha[(size_t)r * N_HEADS + warp] = fminf(a, ALPHA_MAX);
        }
    }
}

// ---------------------------------------------------------------------------
// Round all 4 weight matrices to fp16 in one launch.
// ---------------------------------------------------------------------------
__global__ __launch_bounds__(256) void cvt4_kernel(
    const float* __restrict__ W0, const float* __restrict__ W1,
    const float* __restrict__ W2, const float* __restrict__ W3,
    __half* __restrict__ out)
{
    const int i = blockIdx.x * 256 + threadIdx.x;
    const int sel = i >> 20;
    const int off = i & ((1 << 20) - 1);
    const float* src = (sel == 0) ? W0 : (sel == 1) ? W1 : (sel == 2) ? W2 : W3;
    out[i] = __float2half_rn(src[off]);
}

// ---------------------------------------------------------------------------
// Chunked slim scan: grid (B*H, NSC). Chunk z computes t in [tStart, tEnd)
// with zero state at tStart (tStart = max(0, z*CH - BURN)); emits kf only
// for t >= tEmit = z*CH.  R15 body (f32x2 packed state, cp.async staging).
// ---------------------------------------------------------------------------
#define SCH 16   // timesteps per staging chunk

__global__ __launch_bounds__(64) void scan_kernel(
    const float* __restrict__ k, const float* __restrict__ v,
    const float* __restrict__ alpha, float* __restrict__ kf_out, int T)
{
    const int bh = blockIdx.x;
    const int z  = blockIdx.y;
    const int b = bh / N_HEADS;
    const int h = bh % N_HEADS;
    const int d = threadIdx.x;
    const int warp = d >> 5;
    const int lane = d & 31;

    const int CH = T / NSC;                       // 512
    const int tEmit  = z * CH;
    const int tEnd   = tEmit + CH;
    const int tStart = (z == 0) ? 0 : (tEmit - BURN);   // multiple of 16

    __shared__ float sk[2][SCH][D_HEAD];
    __shared__ float sv[2][SCH][D_HEAD];
    __shared__ float sa[2][SCH];
    __shared__ __align__(16) float sm_ku[2][2][16];  // [buf][warp][r]

    const uint32_t sk_a = smem_u32(sk);
    const uint32_t sv_a = smem_u32(sv);
    const uint32_t sa_a = smem_u32(sa);

    u64t UP[8], VP[8];
    const u64t Z2 = pack2(0.0f, 0.0f);
#pragma unroll
    for (int i = 0; i < 8; i++) { UP[i] = Z2; VP[i] = Z2; }
    const u64t DEC2   = pack2(DECAY, DECAY);
    const u64t NBETA2 = pack2(-BETA, -BETA);

    const int l4 = lane & 15;
    const int rIdx = ((l4 & 1) << 3) | ((l4 & 2) << 1) | ((l4 & 4) >> 1) | ((l4 & 8) >> 3);

    const size_t strideT = (size_t)N_HEADS * D_HEAD;   // 1024
    const size_t kbase = (size_t)b * T * strideT + (size_t)h * D_HEAD;
    const size_t abase = (size_t)b * T * N_HEADS + h;

    auto issue = [&](int c) {     // c indexes SCH-step staging chunks from 0 at tStart
        const int t0 = tStart + c * SCH;
        const uint32_t bufB = (uint32_t)(c & 1) * (SCH * D_HEAD * 4);
#pragma unroll
        for (int i = 0; i < 4; i++) {
            int L = d + (i << 6);            // 0..255
            int s = L >> 4;
            int seg = L & 15;
            const size_t g = kbase + (size_t)(t0 + s) * strideT + seg * 4;
            const uint32_t so = bufB + (uint32_t)s * (D_HEAD * 4) + seg * 16;
            cp_async16(sk_a + so, k + g);
            cp_async16(sv_a + so, v + g);
        }
        if (d < SCH)
            cp_async4(sa_a + (uint32_t)(c & 1) * (SCH * 4) + d * 4,
                      alpha + abase + (size_t)(t0 + d) * N_HEADS);
        CP_COMMIT();
    };

    issue(0);
    issue(1);

    const int NCHK = (tEnd - tStart) / SCH;

    for (int c = 0; c < NCHK; c++) {
        CP_WAIT(1);
        __syncthreads();
        const int buf = c & 1;
        const int t0 = tStart + c * SCH;

        float kt = sk[buf][0][d];
        float vt = sv[buf][0][d];
        float a  = sa[buf][0];

#pragma unroll 4
        for (int s = 0; s < SCH; s++) {
            const int t = t0 + s;
            const int pbuf = t & 1;

            float nk = 0.f, nv = 0.f, na = 0.f;
            if (s + 1 < SCH) {
                nk = sk[buf][s + 1][d];
                nv = sv[buf][s + 1][d];
                na = sa[buf][s + 1];
            }

            const float ktd = kt * DECAY;
            const u64t KTD2 = pack2(ktd, ktd);
            float p[RANK];
#pragma unroll
            for (int i = 0; i < 8; i++) {
                u64t pp = mul2(KTD2, UP[i]);
                unpack2(pp, p[2 * i], p[2 * i + 1]);
            }

#pragma unroll
            for (int st = 1, cnt = 8; st <= 8; st <<= 1, cnt >>= 1) {
                const bool hi = (lane & st) != 0;
#pragma unroll
                for (int i = 0; i < cnt; i++) {
                    float lo_v = p[i], hi_v = p[i + cnt];
                    float send = hi ? lo_v : hi_v;
                    float recv = __shfl_xor_sync(0xFFFFFFFFu, send, st);
                    p[i] = (hi ? hi_v : lo_v) + recv;
                }
            }
            float vr = p[0] + __shfl_xor_sync(0xFFFFFFFFu, p[0], 16);

#pragma unroll
            for (int i = 0; i < 8; i++) {
                UP[i] = mul2(DEC2, UP[i]);
                VP[i] = mul2(DEC2, VP[i]);
            }

            sm_ku[pbuf][warp][rIdx] = vr;
            __syncthreads();

            const float ak = a * kt;
            const float av = a * vt;
            const u64t AK2 = pack2(ak, ak);
            const u64t AV2 = pack2(av, av);
            u64t KF2 = Z2;
#pragma unroll
            for (int i = 0; i < 8; i++) {
                u64t ku2 = add2(*reinterpret_cast<const u64t*>(&sm_ku[pbuf][0][2 * i]),
                                *reinterpret_cast<const u64t*>(&sm_ku[pbuf][1][2 * i]));
                u64t u2 = fma2(AK2, ku2, UP[i]);
                u64t w2 = fma2(AV2, ku2, VP[i]);
                float ul, uh, wl, wh;
                unpack2(u2, ul, uh);
                unpack2(w2, wl, wh);
                const u64t cu2 = pack2(fminf(fmaxf(ul, -1.0f), 1.0f),
                                       fminf(fmaxf(uh, -1.0f), 1.0f));
                const u64t cw2 = pack2(fminf(fmaxf(wl, -1.0f), 1.0f),
                                       fminf(fmaxf(wh, -1.0f), 1.0f));
                u2 = fma2(NBETA2, cu2, u2);
                w2 = fma2(NBETA2, cw2, w2);
                UP[i] = u2;
                VP[i] = w2;
                KF2 = fma2(u2, w2, KF2);
            }
            float kfl, kfh;
            unpack2(KF2, kfl, kfh);

            if (t >= tEmit)
                kf_out[kbase + (size_t)t * strideT + d] = kfl + kfh;

            kt = nk; vt = nv; a = na;
        }

        __syncthreads();
        if (c + 2 < NCHK) issue(c + 2);
        else CP_COMMIT();
    }
}

// ---------------------------------------------------------------------------
// Parallel mix epilogue: y = softmax2(q.k, q.kf) blend of v and kf -> fp16.
// ---------------------------------------------------------------------------
__global__ __launch_bounds__(256) void mix_kernel(
    const float* __restrict__ q, const float* __restrict__ k,
    const float* __restrict__ v, const float* __restrict__ kf,
    __half* __restrict__ yh)
{
    const int row = blockIdx.x;          // b*T + t
    const int warp = threadIdx.x >> 5;   // 0..7
    const int lane = threadIdx.x & 31;

#pragma unroll
    for (int hh = 0; hh < 2; hh++) {
        const int h = warp * 2 + hh;
        const size_t base = (size_t)row * D_MODEL + h * D_HEAD;
        const float q0 = q[base + lane],      q1 = q[base + lane + 32];
        const float k0 = k[base + lane],      k1 = k[base + lane + 32];
        const float f0 = kf[base + lane],     f1 = kf[base + lane + 32];

        float s0 = fmaf(q1, k1, q0 * k0);
        float s1 = fmaf(q1, f1, q0 * f0);
#pragma unroll
        for (int off = 16; off; off >>= 1) {
            s0 += __shfl_xor_sync(0xFFFFFFFFu, s0, off);
            s1 += __shfl_xor_sync(0xFFFFFFFFu, s1, off);
        }
        const float m1 = __fdividef(1.0f, 1.0f + __expf((s0 - s1) * 0.125f));
        const float m0 = 1.0f - m1;

        const float v0 = v[base + lane], v1 = v[base + lane + 32];
        yh[base + lane]      = __float2half_rn(m0 * v0 + m1 * f0);
        yh[base + lane + 32] = __float2half_rn(m0 * v1 + m1 * f1);
    }
}

// ---------------------------------------------------------------------------
// Launch (single stream)
// ---------------------------------------------------------------------------
extern "C" void kernel_launch(void* const* d_in, const int* in_sizes, int n_in,
                              void* d_out, int out_size)
{
    const float* x      = (const float*)d_in[0];
    const float* m_gate = (const float*)d_in[1];
    const float* ascale = (const float*)d_in[2];
    const float* Wq     = (const float*)d_in[3];
    const float* Wk     = (const float*)d_in[4];
    const float* Wv     = (const float*)d_in[5];
    const float* Wo     = (const float*)d_in[6];
    const float* Wa     = (const float*)d_in[7];
    const float* ba     = (const float*)d_in[8];
    // d_in[9] = mix_logit: cancels in the 2-way softmax; unused.
    float* out = (float*)d_out;

    const int M = in_sizes[1] > 0 ? in_sizes[1] : BT;  // B*T
    const int T = M / BB;

    __half *xh, *wf, *yh;
    float *dq, *dk, *dv, *dkf, *da;
    cudaGetSymbolAddress((void**)&xh, g_xh);
    cudaGetSymbolAddress((void**)&wf, g_w);
    cudaGetSymbolAddress((void**)&yh, g_yh);
    cudaGetSymbolAddress((void**)&dq, g_q);
    cudaGetSymbolAddress((void**)&dk, g_k);
    cudaGetSymbolAddress((void**)&dv, g_v);
    cudaGetSymbolAddress((void**)&dkf, g_kf);
    cudaGetSymbolAddress((void**)&da, g_alpha);

    const int DW = D_MODEL * D_MODEL;

    static bool attr_set = false;
    if (!attr_set) {
        cudaFuncSetAttribute(gemm_f16,
                             cudaFuncAttributeMaxDynamicSharedMemorySize, GEMM_SMEM_BYTES);
        cudaFuncSetAttribute(cvtx_alpha_kernel,
                             cudaFuncAttributeMaxDynamicSharedMemorySize, 16 * D_MODEL * 4);
        attr_set = true;
    }

    cvtx_alpha_kernel<<<M / 16, 512, 16 * D_MODEL * 4>>>(
        x, Wa, ba, m_gate, ascale, xh, da);

    cvt4_kernel<<<(4 * DW) / 256, 256>>>(Wq, Wk, Wv, Wo, wf);

    dim3 gqkv(D_MODEL / GN, M / GM, 3);
    gemm_f16<<<gqkv, 256, GEMM_SMEM_BYTES>>>(xh, wf, dq, dk, dv, M, D_MODEL, D_MODEL);

    dim3 gscan(BB * N_HEADS, NSC);
    scan_kernel<<<gscan, 64>>>(dk, dv, da, dkf, T);

    mix_kernel<<<M, 256>>>(dq, dk, dv, dkf, yh);

    dim3 go(D_MODEL / GN, M / GM, 1);
    gemm_f16<<<go, 256, GEMM_SMEM_BYTES>>>(yh, wf + (size_t)3 * DW,
                                           out, out, out, M, D_MODEL, D_MODEL);
}

// round 17
// speedup vs baseline: 2.1477x; 1.0720x over previous
#include <cuda_runtime.h>
#include <cuda_fp16.h>
#include <math.h>
#include <stdint.h>

// ---------------------------------------------------------------------------
// CortexBlock on GB300 (compute_103 pipeline => mma.sync HMMA path)
// B=4, T=2048, D=1024, H=16, Dh=64, R=16
// R16 pipeline, NSC=8 scan chunks (BURN=384), and Q-GEMM overlapped with the
// scan via a second stream (scan needs only k/v/alpha; q first needed by mix).
// ---------------------------------------------------------------------------

#define D_MODEL 1024
#define N_HEADS 16
#define D_HEAD  64
#define RANK    16
#define DECAY   0.95f
#define ALPHA_MAX 0.05f
#define BETA    0.01f

#define BB 4
#define TT 2048
#define BT (BB*TT)   // 8192
#define NSC 8        // scan chunks
#define BURN 384     // warm-up steps for chunks z>0 (clamped at t=0)

// ---------------- scratch (static device globals; no allocs allowed) -------
__device__ __align__(256) __half g_xh[BT * D_MODEL];
__device__ __align__(256) __half g_w[4 * D_MODEL * D_MODEL];   // Wq,Wk,Wv,Wo fp16
__device__ __align__(256) __half g_yh[BT * D_MODEL];
__device__ __align__(256) float g_q[BT * D_MODEL];
__device__ __align__(256) float g_k[BT * D_MODEL];
__device__ __align__(256) float g_v[BT * D_MODEL];
__device__ __align__(256) float g_kf[BT * D_MODEL];
__device__ __align__(256) float g_alpha[BT * N_HEADS];

// ---------------- small asm helpers ----------------------------------------
typedef unsigned long long u64t;
__device__ __forceinline__ u64t pack2(float lo, float hi) {
    u64t r; asm("mov.b64 %0, {%1, %2};" : "=l"(r) : "f"(lo), "f"(hi)); return r;
}
__device__ __forceinline__ void unpack2(u64t p, float& lo, float& hi) {
    asm("mov.b64 {%0, %1}, %2;" : "=f"(lo), "=f"(hi) : "l"(p));
}
__device__ __forceinline__ u64t fma2(u64t a, u64t b, u64t c) {
    u64t d; asm("fma.rn.f32x2 %0, %1, %2, %3;" : "=l"(d) : "l"(a), "l"(b), "l"(c)); return d;
}
__device__ __forceinline__ u64t mul2(u64t a, u64t b) {
    u64t d; asm("mul.rn.f32x2 %0, %1, %2;" : "=l"(d) : "l"(a), "l"(b)); return d;
}
__device__ __forceinline__ u64t add2(u64t a, u64t b) {
    u64t d; asm("add.rn.f32x2 %0, %1, %2;" : "=l"(d) : "l"(a), "l"(b)); return d;
}

__device__ __forceinline__ uint32_t smem_u32(const void* p) {
    uint32_t a;
    asm("{ .reg .u64 t; cvta.to.shared.u64 t, %1; cvt.u32.u64 %0, t; }"
        : "=r"(a) : "l"(p));
    return a;
}
__device__ __forceinline__ void cp_async16(uint32_t daddr, const void* gaddr) {
    asm volatile("cp.async.cg.shared.global [%0], [%1], 16;"
                 :: "r"(daddr), "l"(gaddr) : "memory");
}
__device__ __forceinline__ void cp_async4(uint32_t daddr, const void* gaddr) {
    asm volatile("cp.async.ca.shared.global [%0], [%1], 4;"
                 :: "r"(daddr), "l"(gaddr) : "memory");
}
#define CP_COMMIT()  asm volatile("cp.async.commit_group;" ::: "memory")
#define CP_WAIT(n)   asm volatile("cp.async.wait_group %0;" :: "n"(n) : "memory")

__device__ __forceinline__ void ldsm_x4(uint32_t (&r)[4], uint32_t addr) {
    asm volatile("ldmatrix.sync.aligned.m8n8.x4.shared.b16 {%0,%1,%2,%3}, [%4];"
                 : "=r"(r[0]), "=r"(r[1]), "=r"(r[2]), "=r"(r[3]) : "r"(addr));
}
__device__ __forceinline__ void mma_16816_f16(float (&d)[4], const uint32_t (&a)[4],
                                              uint32_t b0, uint32_t b1) {
    asm volatile(
        "mma.sync.aligned.m16n8k16.row.col.f32.f16.f16.f32 "
        "{%0,%1,%2,%3}, {%4,%5,%6,%7}, {%8,%9}, {%0,%1,%2,%3};"
        : "+f"(d[0]), "+f"(d[1]), "+f"(d[2]), "+f"(d[3])
        : "r"(a[0]), "r"(a[1]), "r"(a[2]), "r"(a[3]), "r"(b0), "r"(b1));
}

// ---------------------------------------------------------------------------
// fp16 single-pass GEMM (R8 config): C[M,N](fp32) = A[M,K] * W[N,K]^T
// CTA tile 128x128, K-chunk 64, 4-stage cp.async, 1 barrier/chunk.
// ---------------------------------------------------------------------------
#define GM 128
#define GN 128
#define GKC 64
#define AST 72
#define TILE_HALVES (GM * AST)
#define TILE_BYTES  (TILE_HALVES * 2)
#define STAGE_BYTES (2 * TILE_BYTES)
#define NSTAGE 4
#define GEMM_SMEM_BYTES (NSTAGE * STAGE_BYTES)   // 147456

__global__ __launch_bounds__(256, 1) void gemm_f16(
    const __half* __restrict__ A, const __half* __restrict__ Wbase,
    float* __restrict__ C0, float* __restrict__ C1, float* __restrict__ C2,
    int M, int N, int K)
{
    extern __shared__ __half smem[];

    const int tid  = threadIdx.x;
    const int wid  = tid >> 5;
    const int lane = tid & 31;
    const int rowBase = blockIdx.y * GM;
    const int colBase = blockIdx.x * GN;
    const int z = blockIdx.z;

    const __half* Bw = Wbase + (size_t)z * D_MODEL * D_MODEL;
    float* C = (z == 0) ? C0 : (z == 1) ? C1 : C2;

    const int wm = (wid >> 2) * 64;
    const int wn = (wid & 3) * 32;

    const uint32_t smBase = smem_u32(smem);

    float acc[4][4][4];
#pragma unroll
    for (int i = 0; i < 4; i++)
#pragma unroll
        for (int j = 0; j < 4; j++)
#pragma unroll
            for (int c = 0; c < 4; c++) acc[i][j][c] = 0.0f;

    const int aRow = lane & 15;
    const int aKo  = (lane >> 4) * 8;
    const int bNo  = ((lane >> 4) << 3) + (lane & 7);
    const int bKo  = ((lane >> 3) & 1) * 8;

    const int NCH = K / GKC;

    auto issue = [&](int ci) {
        const int k0 = ci * GKC;
        const uint32_t stage = smBase + (uint32_t)(ci % NSTAGE) * STAGE_BYTES;
#pragma unroll
        for (int i = 0; i < 4; i++) {
            int L = tid + (i << 8);
            int row = L >> 3;
            int seg = L & 7;
            uint32_t off = (uint32_t)row * (AST * 2) + seg * 16;
            cp_async16(stage + off,
                       A + (size_t)(rowBase + row) * K + k0 + seg * 8);
            cp_async16(stage + TILE_BYTES + off,
                       Bw + (size_t)(colBase + row) * K + k0 + seg * 8);
        }
        CP_COMMIT();
    };

    issue(0);
    issue(1);
    issue(2);

    for (int ci = 0; ci < NCH; ci++) {
        CP_WAIT(2);
        __syncthreads();
        if (ci + 3 < NCH) issue(ci + 3);
        else CP_COMMIT();

        const uint32_t stage  = smBase + (uint32_t)(ci % NSTAGE) * STAGE_BYTES;
        const uint32_t bBase0 = stage + TILE_BYTES;

#pragma unroll
        for (int ks = 0; ks < 4; ks++) {
            uint32_t Ar[4][4];
#pragma unroll
            for (int mi = 0; mi < 4; mi++) {
                uint32_t addr = stage + (uint32_t)(wm + mi * 16 + aRow) * (AST * 2)
                              + (uint32_t)(ks * 16 + aKo) * 2;
                ldsm_x4(Ar[mi], addr);
            }
            uint32_t Br[2][4];
#pragma unroll
            for (int ni = 0; ni < 2; ni++) {
                uint32_t addr = bBase0 + (uint32_t)(wn + ni * 16 + bNo) * (AST * 2)
                              + (uint32_t)(ks * 16 + bKo) * 2;
                ldsm_x4(Br[ni], addr);
            }
#pragma unroll
            for (int mi = 0; mi < 4; mi++)
#pragma unroll
                for (int j = 0; j < 4; j++)
                    mma_16816_f16(acc[mi][j], Ar[mi],
                                  Br[j >> 1][(j & 1) * 2], Br[j >> 1][(j & 1) * 2 + 1]);
        }
    }

#pragma unroll
    for (int mi = 0; mi < 4; mi++) {
        const int row0 = rowBase + wm + mi * 16 + (lane >> 2);
#pragma unroll
        for (int j = 0; j < 4; j++) {
            const int col = colBase + wn + j * 8 + (lane & 3) * 2;
            *reinterpret_cast<float2*>(C + (size_t)row0 * N + col) =
                make_float2(acc[mi][j][0], acc[mi][j][1]);
            *reinterpret_cast<float2*>(C + (size_t)(row0 + 8) * N + col) =
                make_float2(acc[mi][j][2], acc[mi][j][3]);
        }
    }
}

// ---------------------------------------------------------------------------
// Fused x->fp16 convert + alpha. Block = 16 rows, 512 threads.
// ---------------------------------------------------------------------------
__global__ __launch_bounds__(512) void cvtx_alpha_kernel(
    const float* __restrict__ x, const float* __restrict__ Wa,
    const float* __restrict__ ba, const float* __restrict__ m_gate,
    const float* __restrict__ ascale,
    __half* __restrict__ xh, float* __restrict__ alpha)
{
    extern __shared__ float xs[];        // [16][1024]
    const int tid  = threadIdx.x;
    const int warp = tid >> 5;
    const int lane = tid & 31;
    const int rowBase = blockIdx.x * 16;

    const float4* xg = reinterpret_cast<const float4*>(x + (size_t)rowBase * D_MODEL);
#pragma unroll
    for (int it = 0; it < 8; it++) {
        int i = tid + it * 512;
        float4 v = xg[i];
        reinterpret_cast<float4*>(xs)[i] = v;
        __half2* ph = reinterpret_cast<__half2*>(xh + (size_t)rowBase * D_MODEL + i * 4);
        ph[0] = __half2(__float2half_rn(v.x), __float2half_rn(v.y));
        ph[1] = __half2(__float2half_rn(v.z), __float2half_rn(v.w));
    }
    __syncthreads();

    float wa[32];
#pragma unroll
    for (int i = 0; i < 32; i++)
        wa[i] = Wa[(size_t)warp * D_MODEL + i * 32 + lane];
    const float bw = ba[warp];

#pragma unroll 4
    for (int row = 0; row < 16; row++) {
        const float* xr = xs + row * D_MODEL;
        float s = 0.0f;
#pragma unroll
        for (int i = 0; i < 32; i++)
            s = fmaf(wa[i], xr[i * 32 + lane], s);
#pragma unroll
        for (int off = 16; off; off >>= 1)
            s += __shfl_xor_sync(0xFFFFFFFFu, s, off);
        if (lane == 0) {
            const int r = rowBase + row;
            float sg = __fdividef(1.0f, 1.0f + __expf(-(s + bw)));
            float a = sg * m_gate[r] * ascale[(size_t)r * N_HEADS + warp];
            alpha[(size_t)r * N_HEADS + warp] = fminf(a, ALPHA_MAX);
        }
    }
}

// ---------------------------------------------------------------------------
// Round all 4 weight matrices to fp16 in one launch.
// ---------------------------------------------------------------------------
__global__ __launch_bounds__(256) void cvt4_kernel(
    const float* __restrict__ W0, const float* __restrict__ W1,
    const float* __restrict__ W2, const float* __restrict__ W3,
    __half* __restrict__ out)
{
    const int i = blockIdx.x * 256 + threadIdx.x;
    const int sel = i >> 20;
    const int off = i & ((1 << 20) - 1);
    const float* src = (sel == 0) ? W0 : (sel == 1) ? W1 : (sel == 2) ? W2 : W3;
    out[i] = __float2half_rn(src[off]);
}

// ---------------------------------------------------------------------------
// Chunked slim scan: grid (B*H, NSC). Chunk z computes t in [tStart, tEnd)
// with zero state at tStart = max(0, z*CH - BURN); emits kf for t >= z*CH.
// ---------------------------------------------------------------------------
#define SCH 16   // timesteps per staging chunk

__global__ __launch_bounds__(64) void scan_kernel(
    const float* __restrict__ k, const float* __restrict__ v,
    const float* __restrict__ alpha, float* __restrict__ kf_out, int T)
{
    const int bh = blockIdx.x;
    const int z  = blockIdx.y;
    const int b = bh / N_HEADS;
    const int h = bh % N_HEADS;
    const int d = threadIdx.x;
    const int warp = d >> 5;
    const int lane = d & 31;

    const int CH = T / NSC;                       // 256
    const int tEmit  = z * CH;
    const int tEnd   = tEmit + CH;
    int tStart = tEmit - BURN;
    if (tStart < 0) tStart = 0;                   // multiple of 16 either way

    __shared__ float sk[2][SCH][D_HEAD];
    __shared__ float sv[2][SCH][D_HEAD];
    __shared__ float sa[2][SCH];
    __shared__ __align__(16) float sm_ku[2][2][16];  // [buf][warp][r]

    const uint32_t sk_a = smem_u32(sk);
    const uint32_t sv_a = smem_u32(sv);
    const uint32_t sa_a = smem_u32(sa);

    u64t UP[8], VP[8];
    const u64t Z2 = pack2(0.0f, 0.0f);
#pragma unroll
    for (int i = 0; i < 8; i++) { UP[i] = Z2; VP[i] = Z2; }
    const u64t DEC2   = pack2(DECAY, DECAY);
    const u64t NBETA2 = pack2(-BETA, -BETA);

    const int l4 = lane & 15;
    const int rIdx = ((l4 & 1) << 3) | ((l4 & 2) << 1) | ((l4 & 4) >> 1) | ((l4 & 8) >> 3);

    const size_t strideT = (size_t)N_HEADS * D_HEAD;   // 1024
    const size_t kbase = (size_t)b * T * strideT + (size_t)h * D_HEAD;
    const size_t abase = (size_t)b * T * N_HEADS + h;

    auto issue = [&](int c) {
        const int t0 = tStart + c * SCH;
        const uint32_t bufB = (uint32_t)(c & 1) * (SCH * D_HEAD * 4);
#pragma unroll
        for (int i = 0; i < 4; i++) {
            int L = d + (i << 6);            // 0..255
            int s = L >> 4;
            int seg = L & 15;
            const size_t g = kbase + (size_t)(t0 + s) * strideT + seg * 4;
            const uint32_t so = bufB + (uint32_t)s * (D_HEAD * 4) + seg * 16;
            cp_async16(sk_a + so, k + g);
            cp_async16(sv_a + so, v + g);
        }
        if (d < SCH)
            cp_async4(sa_a + (uint32_t)(c & 1) * (SCH * 4) + d * 4,
                      alpha + abase + (size_t)(t0 + d) * N_HEADS);
        CP_COMMIT();
    };

    issue(0);
    issue(1);

    const int NCHK = (tEnd - tStart) / SCH;

    for (int c = 0; c < NCHK; c++) {
        CP_WAIT(1);
        __syncthreads();
        const int buf = c & 1;
        const int t0 = tStart + c * SCH;

        float kt = sk[buf][0][d];
        float vt = sv[buf][0][d];
        float a  = sa[buf][0];

#pragma unroll 4
        for (int s = 0; s < SCH; s++) {
            const int t = t0 + s;
            const int pbuf = t & 1;

            float nk = 0.f, nv = 0.f, na = 0.f;
            if (s + 1 < SCH) {
                nk = sk[buf][s + 1][d];
                nv = sv[buf][s + 1][d];
                na = sa[buf][s + 1];
            }

            const float ktd = kt * DECAY;
            const u64t KTD2 = pack2(ktd, ktd);
            float p[RANK];
#pragma unroll
            for (int i = 0; i < 8; i++) {
                u64t pp = mul2(KTD2, UP[i]);
                unpack2(pp, p[2 * i], p[2 * i + 1]);
            }

#pragma unroll
            for (int st = 1, cnt = 8; st <= 8; st <<= 1, cnt >>= 1) {
                const bool hi = (lane & st) != 0;
#pragma unroll
                for (int i = 0; i < cnt; i++) {
                    float lo_v = p[i], hi_v = p[i + cnt];
                    float send = hi ? lo_v : hi_v;
                    float recv = __shfl_xor_sync(0xFFFFFFFFu, send, st);
                    p[i] = (hi ? hi_v : lo_v) + recv;
                }
            }
            float vr = p[0] + __shfl_xor_sync(0xFFFFFFFFu, p[0], 16);

#pragma unroll
            for (int i = 0; i < 8; i++) {
                UP[i] = mul2(DEC2, UP[i]);
                VP[i] = mul2(DEC2, VP[i]);
            }

            sm_ku[pbuf][warp][rIdx] = vr;
            __syncthreads();

            const float ak = a * kt;
            const float av = a * vt;
            const u64t AK2 = pack2(ak, ak);
            const u64t AV2 = pack2(av, av);
            u64t KF2 = Z2;
#pragma unroll
            for (int i = 0; i < 8; i++) {
                u64t ku2 = add2(*reinterpret_cast<const u64t*>(&sm_ku[pbuf][0][2 * i]),
                                *reinterpret_cast<const u64t*>(&sm_ku[pbuf][1][2 * i]));
                u64t u2 = fma2(AK2, ku2, UP[i]);
                u64t w2 = fma2(AV2, ku2, VP[i]);
                float ul, uh, wl, wh;
                unpack2(u2, ul, uh);
                unpack2(w2, wl, wh);
                const u64t cu2 = pack2(fminf(fmaxf(ul, -1.0f), 1.0f),
                                       fminf(fmaxf(uh, -1.0f), 1.0f));
                const u64t cw2 = pack2(fminf(fmaxf(wl, -1.0f), 1.0f),
                                       fminf(fmaxf(wh, -1.0f), 1.0f));
                u2 = fma2(NBETA2, cu2, u2);
                w2 = fma2(NBETA2, cw2, w2);
                UP[i] = u2;
                VP[i] = w2;
                KF2 = fma2(u2, w2, KF2);
            }
            float kfl, kfh;
            unpack2(KF2, kfl, kfh);

            if (t >= tEmit)
                kf_out[kbase + (size_t)t * strideT + d] = kfl + kfh;

            kt = nk; vt = nv; a = na;
        }

        __syncthreads();
        if (c + 2 < NCHK) issue(c + 2);
        else CP_COMMIT();
    }
}

// ---------------------------------------------------------------------------
// Parallel mix epilogue: y = softmax2(q.k, q.kf) blend of v and kf -> fp16.
// ---------------------------------------------------------------------------
__global__ __launch_bounds__(256) void mix_kernel(
    const float* __restrict__ q, const float* __restrict__ k,
    const float* __restrict__ v, const float* __restrict__ kf,
    __half* __restrict__ yh)
{
    const int row = blockIdx.x;          // b*T + t
    const int warp = threadIdx.x >> 5;   // 0..7
    const int lane = threadIdx.x & 31;

#pragma unroll
    for (int hh = 0; hh < 2; hh++) {
        const int h = warp * 2 + hh;
        const size_t base = (size_t)row * D_MODEL + h * D_HEAD;
        const float q0 = q[base + lane],      q1 = q[base + lane + 32];
        const float k0 = k[base + lane],      k1 = k[base + lane + 32];
        const float f0 = kf[base + lane],     f1 = kf[base + lane + 32];

        float s0 = fmaf(q1, k1, q0 * k0);
        float s1 = fmaf(q1, f1, q0 * f0);
#pragma unroll
        for (int off = 16; off; off >>= 1) {
            s0 += __shfl_xor_sync(0xFFFFFFFFu, s0, off);
            s1 += __shfl_xor_sync(0xFFFFFFFFu, s1, off);
        }
        const float m1 = __fdividef(1.0f, 1.0f + __expf((s0 - s1) * 0.125f));
        const float m0 = 1.0f - m1;

        const float v0 = v[base + lane], v1 = v[base + lane + 32];
        yh[base + lane]      = __float2half_rn(m0 * v0 + m1 * f0);
        yh[base + lane + 32] = __float2half_rn(m0 * v1 + m1 * f1);
    }
}

// ---------------------------------------------------------------------------
// Stream/event objects (created at static init; host-side only).
// ---------------------------------------------------------------------------
struct PipeObjs {
    cudaStream_t s1;
    cudaEvent_t ev_kv, ev_scan;
    PipeObjs() {
        cudaStreamCreateWithFlags(&s1, cudaStreamNonBlocking);
        cudaEventCreateWithFlags(&ev_kv, cudaEventDisableTiming);
        cudaEventCreateWithFlags(&ev_scan, cudaEventDisableTiming);
    }
};
static PipeObjs g_pipe;

// ---------------------------------------------------------------------------
// Launch: prep -> KV GEMM -> (scan on s1 || Q GEMM on s0) -> mix -> O GEMM
// ---------------------------------------------------------------------------
extern "C" void kernel_launch(void* const* d_in, const int* in_sizes, int n_in,
                              void* d_out, int out_size)
{
    const float* x      = (const float*)d_in[0];
    const float* m_gate = (const float*)d_in[1];
    const float* ascale = (const float*)d_in[2];
    const float* Wq     = (const float*)d_in[3];
    const float* Wk     = (const float*)d_in[4];
    const float* Wv     = (const float*)d_in[5];
    const float* Wo     = (const float*)d_in[6];
    const float* Wa     = (const float*)d_in[7];
    const float* ba     = (const float*)d_in[8];
    // d_in[9] = mix_logit: cancels in the 2-way softmax; unused.
    float* out = (float*)d_out;

    const int M = in_sizes[1] > 0 ? in_sizes[1] : BT;  // B*T
    const int T = M / BB;

    __half *xh, *wf, *yh;
    float *dq, *dk, *dv, *dkf, *da;
    cudaGetSymbolAddress((void**)&xh, g_xh);
    cudaGetSymbolAddress((void**)&wf, g_w);
    cudaGetSymbolAddress((void**)&yh, g_yh);
    cudaGetSymbolAddress((void**)&dq, g_q);
    cudaGetSymbolAddress((void**)&dk, g_k);
    cudaGetSymbolAddress((void**)&dv, g_v);
    cudaGetSymbolAddress((void**)&dkf, g_kf);
    cudaGetSymbolAddress((void**)&da, g_alpha);

    const int DW = D_MODEL * D_MODEL;

    static bool attr_set = false;
    if (!attr_set) {
        cudaFuncSetAttribute(gemm_f16,
                             cudaFuncAttributeMaxDynamicSharedMemorySize, GEMM_SMEM_BYTES);
        cudaFuncSetAttribute(cvtx_alpha_kernel,
                             cudaFuncAttributeMaxDynamicSharedMemorySize, 16 * D_MODEL * 4);
        attr_set = true;
    }

    // prep (stream0)
    cvtx_alpha_kernel<<<M / 16, 512, 16 * D_MODEL * 4>>>(
        x, Wa, ba, m_gate, ascale, xh, da);
    cvt4_kernel<<<(4 * DW) / 256, 256>>>(Wq, Wk, Wv, Wo, wf);

    // K,V projections (Wbase = wf + DW -> z0:Wk, z1:Wv)
    dim3 gkv(D_MODEL / GN, M / GM, 2);
    gemm_f16<<<gkv, 256, GEMM_SMEM_BYTES>>>(xh, wf + (size_t)DW,
                                            dk, dv, dv, M, D_MODEL, D_MODEL);
    cudaEventRecord(g_pipe.ev_kv, 0);

    // scan on stream1 (needs only k, v, alpha)
    cudaStreamWaitEvent(g_pipe.s1, g_pipe.ev_kv, 0);
    dim3 gscan(BB * N_HEADS, NSC);
    scan_kernel<<<gscan, 64, 0, g_pipe.s1>>>(dk, dv, da, dkf, T);
    cudaEventRecord(g_pipe.ev_scan, g_pipe.s1);

    // Q projection on stream0, concurrent with the scan
    dim3 gq(D_MODEL / GN, M / GM, 1);
    gemm_f16<<<gq, 256, GEMM_SMEM_BYTES>>>(xh, wf,
                                           dq, dq, dq, M, D_MODEL, D_MODEL);

    // join: mix needs q (s0) and kf (s1)
    cudaStreamWaitEvent(0, g_pipe.ev_scan, 0);
    mix_kernel<<<M, 256>>>(dq, dk, dv, dkf, yh);

    dim3 go(D_MODEL / GN, M / GM, 1);
    gemm_f16<<<go, 256, GEMM_SMEM_BYTES>>>(yh, wf + (size_t)3 * DW,
                                           out, out, out, M, D_MODEL, D_MODEL);
}